// round 5
// baseline (speedup 1.0000x reference)
#include <cuda_runtime.h>
#include <cuda_bf16.h>
#include <math.h>
#include <stdint.h>

#define H   32
#define SEQ 2048
#define DH  128
#define NOUT 16
#define QMAXF 7.0f

// ---------------------------------------------------------------------------
// Scratch globals
// ---------------------------------------------------------------------------
__device__ float g_vfull[(size_t)H * SEQ * DH];
__device__ __align__(16) __nv_bfloat16 g_khiT[(size_t)H * DH * SEQ];  // [h][d][s]
__device__ __align__(16) __nv_bfloat16 g_kloT[(size_t)H * DH * SEQ];
__device__ __align__(16) __nv_bfloat16 g_khi[(size_t)H * SEQ * DH];   // [h][s][d]
__device__ __align__(16) __nv_bfloat16 g_klo[(size_t)H * SEQ * DH];
__device__ __align__(16) __nv_bfloat16 g_vthi[(size_t)H * DH * SEQ];  // [h][d][s]
__device__ __align__(16) __nv_bfloat16 g_vtlo[(size_t)H * DH * SEQ];

static __device__ __forceinline__ uint32_t pack_bf16(__nv_bfloat16 a, __nv_bfloat16 b) {
    return (uint32_t)__bfloat16_as_ushort(a) | ((uint32_t)__bfloat16_as_ushort(b) << 16);
}
__device__ __forceinline__ uint32_t smem_u32(const void* p) {
    uint32_t a;
    asm("{ .reg .u64 t; cvta.to.shared.u64 t, %1; cvt.u32.u64 %0, t; }" : "=r"(a) : "l"(p));
    return a;
}
__device__ __forceinline__ void ldmx4(uint32_t& r0, uint32_t& r1, uint32_t& r2, uint32_t& r3,
                                      uint32_t addr) {
    asm volatile("ldmatrix.sync.aligned.m8n8.x4.shared.b16 {%0,%1,%2,%3}, [%4];"
                 : "=r"(r0), "=r"(r1), "=r"(r2), "=r"(r3) : "r"(addr));
}
__device__ __forceinline__ void mma_bf16(float* c, const uint32_t* a, uint32_t b0, uint32_t b1) {
    asm volatile("mma.sync.aligned.m16n8k16.row.col.f32.bf16.bf16.f32 "
                 "{%0,%1,%2,%3}, {%4,%5,%6,%7}, {%8,%9}, {%0,%1,%2,%3};"
                 : "+f"(c[0]), "+f"(c[1]), "+f"(c[2]), "+f"(c[3])
                 : "r"(a[0]), "r"(a[1]), "r"(a[2]), "r"(a[3]), "r"(b0), "r"(b1));
}
#define CP_ASYNC16(dst, src) do { \
    size_t _g = __cvta_generic_to_global((const void*)(src)); \
    asm volatile("cp.async.cg.shared.global [%0], [%1], 16;" :: "r"(dst), "l"(_g) : "memory"); \
} while (0)
#define CP_COMMIT() asm volatile("cp.async.commit_group;" ::: "memory")
#define CP_WAIT1()  asm volatile("cp.async.wait_group 1;" ::: "memory")

// ---------------------------------------------------------------------------
// K quantization, incremental argmax. One block per (h, d) slice.
// Writes K^T hi/lo [h][d][s] (coalesced).
// ---------------------------------------------------------------------------
__global__ __launch_bounds__(256) void kquant_kernel(const float* __restrict__ kin) {
    const int slice = blockIdx.x;
    const int h = slice >> 7;
    const int d = slice & 127;
    const int tid = threadIdx.x;
    const int lane = tid & 31, wid = tid >> 5;

    __shared__ float sval[SEQ];
    __shared__ float sabs[SEQ];      // flagged entries set to -1
    __shared__ float swv[8];
    __shared__ int   swi[8];
    __shared__ int   sgi;
    __shared__ float sgv;

    const float* base = kin + (size_t)h * SEQ * DH + d;
    float amax = -1.0f; int aidx = 0;
#pragma unroll
    for (int j = 0; j < 8; ++j) {
        int i = tid + 256 * j;
        float v = base[(size_t)i * DH];
        sval[i] = v;
        float a = fabsf(v);
        sabs[i] = a;
        if (a > amax) { amax = a; aidx = i; }
    }
    __syncthreads();

    for (int it = 0; it < NOUT; ++it) {
        float bv = amax; int bi = aidx;
#pragma unroll
        for (int o = 16; o > 0; o >>= 1) {
            float ov = __shfl_xor_sync(0xffffffffu, bv, o);
            int   oi = __shfl_xor_sync(0xffffffffu, bi, o);
            if (ov > bv || (ov == bv && oi < bi)) { bv = ov; bi = oi; }
        }
        if (lane == 0) { swv[wid] = bv; swi[wid] = bi; }
        __syncthreads();
        if (tid < 8) {
            float v2 = swv[tid]; int i2 = swi[tid];
#pragma unroll
            for (int o = 4; o > 0; o >>= 1) {
                float ov = __shfl_xor_sync(0xffu, v2, o, 8);
                int   oi = __shfl_xor_sync(0xffu, i2, o, 8);
                if (ov > v2 || (ov == v2 && oi < i2)) { v2 = ov; i2 = oi; }
            }
            if (tid == 0) sgi = i2;
        }
        __syncthreads();
        int g = sgi;
        if ((g & 255) == tid) {
            sabs[g] = -1.0f;
            amax = -1.0f; aidx = 0;
#pragma unroll
            for (int j = 0; j < 8; ++j) {
                int i = tid + 256 * j;
                float a = sabs[i];
                if (a > amax) { amax = a; aidx = i; }
            }
        }
        // next reduction uses registers only; swv/sgi rewrites are fenced by the
        // two syncs inside the next iteration.
    }

    // dense max over remaining
    {
        float bv = amax;
#pragma unroll
        for (int o = 16; o > 0; o >>= 1) bv = fmaxf(bv, __shfl_xor_sync(0xffffffffu, bv, o));
        __syncthreads();
        if (lane == 0) swv[wid] = bv;
        __syncthreads();
        if (tid == 0) {
            float mx = swv[0];
#pragma unroll
            for (int j = 1; j < 8; ++j) mx = fmaxf(mx, swv[j]);
            sgv = mx;
        }
        __syncthreads();
    }
    const float scale = fmaxf(sgv, 1e-6f) / QMAXF;

    __nv_bfloat16* khT = g_khiT + ((size_t)h * DH + d) * SEQ;
    __nv_bfloat16* klT = g_kloT + ((size_t)h * DH + d) * SEQ;
#pragma unroll
    for (int j = 0; j < 8; ++j) {
        int i = tid + 256 * j;
        float v = sval[i];
        float o;
        if (sabs[i] < 0.0f) o = v;                        // outlier, exact
        else {
            float qq = rintf(__fdiv_rn(v, scale));
            qq = fminf(fmaxf(qq, -QMAXF), QMAXF);
            o = qq * scale;
        }
        __nv_bfloat16 hi = __float2bfloat16_rn(o);
        __nv_bfloat16 lo = __float2bfloat16_rn(o - __bfloat162float(hi));
        khT[i] = hi;
        klT[i] = lo;
    }
}

// ---------------------------------------------------------------------------
// K transpose: bf16 hi/lo [h][d][s] -> [h][s][d]
// ---------------------------------------------------------------------------
__global__ void ktrans_kernel() {
    __shared__ uint32_t t[32][33];
    const int s0 = blockIdx.x * 32, d0 = blockIdx.y * 32, h = blockIdx.z;
    const int tx = threadIdx.x, ty = threadIdx.y;
    size_t ri = ((size_t)h * DH + d0 + ty) * SEQ + s0 + tx;
    t[ty][tx] = pack_bf16(g_khiT[ri], g_kloT[ri]);
    __syncthreads();
    uint32_t u = t[tx][ty];                 // (d = d0+tx, s = s0+ty)
    size_t o = ((size_t)h * SEQ + s0 + ty) * DH + d0 + tx;
    g_khi[o] = __ushort_as_bfloat16((unsigned short)(u & 0xffffu));
    g_klo[o] = __ushort_as_bfloat16((unsigned short)(u >> 16));
}

// ---------------------------------------------------------------------------
// V quantization: one 128-thread block per (h, s) row.
// ---------------------------------------------------------------------------
__global__ __launch_bounds__(128) void vquant_kernel(const float* __restrict__ vin) {
    const int row = blockIdx.x;
    const int tid = threadIdx.x;

    float v = vin[(size_t)row * DH + tid];
    float a = fabsf(v);

    __shared__ float sab[DH];
    sab[tid] = a;
    __syncthreads();

    int rank = 0;
#pragma unroll 8
    for (int j = 0; j < DH; ++j) {
        float b = sab[j];
        rank += (b > a) || (b == a && j < tid);
    }
    const bool outl = (rank < NOUT);

    float da = outl ? 0.0f : a;
#pragma unroll
    for (int o = 16; o > 0; o >>= 1) da = fmaxf(da, __shfl_xor_sync(0xffffffffu, da, o));
    __shared__ float wmax[4];
    if ((tid & 31) == 0) wmax[tid >> 5] = da;
    __syncthreads();
    float mx = fmaxf(fmaxf(wmax[0], wmax[1]), fmaxf(wmax[2], wmax[3]));
    float scale = fmaxf(mx, 1e-6f) / QMAXF;

    float o;
    if (outl) o = v;
    else {
        float qq = rintf(__fdiv_rn(v, scale));
        qq = fminf(fmaxf(qq, -QMAXF), QMAXF);
        o = qq * scale;
    }
    g_vfull[(size_t)row * DH + tid] = o;
}

// ---------------------------------------------------------------------------
// V transpose + split: fp32 [h][s][d] -> bf16 hi/lo [h][d][s]
// ---------------------------------------------------------------------------
__global__ void vtrans_kernel() {
    __shared__ float t[32][33];
    const int s0 = blockIdx.x * 32, d0 = blockIdx.y * 32, h = blockIdx.z;
    const int tx = threadIdx.x, ty = threadIdx.y;
    t[ty][tx] = g_vfull[((size_t)h * SEQ + s0 + ty) * DH + d0 + tx];
    __syncthreads();
    float v = t[tx][ty];
    __nv_bfloat16 hi = __float2bfloat16_rn(v);
    __nv_bfloat16 lo = __float2bfloat16_rn(v - __bfloat162float(hi));
    size_t o = ((size_t)h * DH + d0 + ty) * SEQ + s0 + tx;
    g_vthi[o] = hi;
    g_vtlo[o] = lo;
}

// ---------------------------------------------------------------------------
// FA2 split-bf16 mma.sync flash attention, BM=128 (8 warps), BN=64,
// 2-stage cp.async pipeline, ldmatrix.x4.
// Stage layout (bytes, per stage of 71680):
//   sKhi [64][272B] @0        sKlo @17408
//   sVhi [128][144B] @34816   sVlo @53248
// Q fp32 staging [128][132] floats overlays stage 1 (offset 71680).
// ---------------------------------------------------------------------------
#define SK_HI 0
#define SK_LO 17408
#define SV_HI 34816
#define SV_LO 53248
#define STAGE_SZ 71680
#define Q_OFF 71680
#define ATTN_SMEM (2 * STAGE_SZ)
#define KSTRB 272
#define VSTRB 144

extern __shared__ char sm_dyn[];

__global__ __launch_bounds__(256, 1)
void attn_mma_kernel(const float* __restrict__ qin, float* __restrict__ out) {
    const uint32_t sb = smem_u32(sm_dyn);
    const int tid  = threadIdx.x;
    const int w    = tid >> 5;
    const int lane = tid & 31;
    const int bx = blockIdx.x;
    const int h  = bx & 31;
    const int qt = 15 - (bx >> 5);          // heavy tiles first
    const int qglob = qt * 128;
    const int ktiles = 2 * qt + 2;

    const int quad = lane >> 2;
    const int qtr  = lane & 3;
    const int r0 = w * 16 + quad;
    const int rowg0 = qglob + r0;
    const int rowg1 = rowg0 + 8;

    const __nv_bfloat16* khi_h = g_khi + (size_t)h * SEQ * DH;
    const __nv_bfloat16* klo_h = g_klo + (size_t)h * SEQ * DH;
    const __nv_bfloat16* vhi_h = g_vthi + (size_t)h * DH * SEQ;
    const __nv_bfloat16* vlo_h = g_vtlo + (size_t)h * DH * SEQ;

    // tile loader: 16 cp.async per thread
    auto issue_tile = [&](int stage, int kt) {
        uint32_t d32 = sb + stage * STAGE_SZ;
        const uint4* kb0 = (const uint4*)(khi_h + (size_t)kt * 64 * DH);
        const uint4* kb1 = (const uint4*)(klo_h + (size_t)kt * 64 * DH);
#pragma unroll
        for (int i = tid; i < 1024; i += 256) {
            int r = i >> 4, c = i & 15;
            uint32_t sa = r * KSTRB + c * 16;
            CP_ASYNC16(d32 + SK_HI + sa, kb0 + r * 16 + c);
            CP_ASYNC16(d32 + SK_LO + sa, kb1 + r * 16 + c);
        }
        const __nv_bfloat16* vb0 = vhi_h + (size_t)kt * 64;
        const __nv_bfloat16* vb1 = vlo_h + (size_t)kt * 64;
#pragma unroll
        for (int i = tid; i < 1024; i += 256) {
            int r = i >> 3, c = i & 7;
            uint32_t sa = r * VSTRB + c * 16;
            CP_ASYNC16(d32 + SV_HI + sa, (const uint4*)(vb0 + (size_t)r * SEQ) + c);
            CP_ASYNC16(d32 + SV_LO + sa, (const uint4*)(vb1 + (size_t)r * SEQ) + c);
        }
    };

    // prologue: kick tile 0 into stage 0
    issue_tile(0, 0);
    CP_COMMIT();

    // ---- stage Q (scaled) fp32 into overlay, build A-fragments ----
    float* sQf = (float*)(sm_dyn + Q_OFF);
    {
        const float sms = 0.08838834764831845f;
        const float4* qbase = (const float4*)(qin + ((size_t)h * SEQ + qglob) * DH);
#pragma unroll
        for (int i = tid; i < 128 * 32; i += 256) {
            int r = i >> 5, c = i & 31;
            float4 v = qbase[r * 32 + c];
            v.x *= sms; v.y *= sms; v.z *= sms; v.w *= sms;
            *(float4*)&sQf[r * 132 + c * 4] = v;
        }
    }
    __syncthreads();

    uint32_t qhi[8][4], qlo[8][4];
    {
        const float* s0 = &sQf[r0 * 132];
        const float* s1 = &sQf[(r0 + 8) * 132];
#pragma unroll
        for (int kf = 0; kf < 8; ++kf) {
            int k0 = kf * 16 + 2 * qtr;
            float e[4][2] = {{s0[k0], s0[k0 + 1]}, {s1[k0], s1[k0 + 1]},
                             {s0[k0 + 8], s0[k0 + 9]}, {s1[k0 + 8], s1[k0 + 9]}};
#pragma unroll
            for (int j = 0; j < 4; ++j) {
                __nv_bfloat16 h0 = __float2bfloat16_rn(e[j][0]);
                __nv_bfloat16 h1 = __float2bfloat16_rn(e[j][1]);
                __nv_bfloat16 l0 = __float2bfloat16_rn(e[j][0] - __bfloat162float(h0));
                __nv_bfloat16 l1 = __float2bfloat16_rn(e[j][1] - __bfloat162float(h1));
                qhi[kf][j] = pack_bf16(h0, h1);
                qlo[kf][j] = pack_bf16(l0, l1);
            }
        }
    }
    __syncthreads();   // Q overlay region free; stage-1 cp.async may now target it

    const int l8 = lane & 7;
    const int lg = (lane >> 3) & 3;

    float O[16][4];
#pragma unroll
    for (int i = 0; i < 16; ++i)
#pragma unroll
        for (int j = 0; j < 4; ++j) O[i][j] = 0.0f;
    float m0 = -INFINITY, m1 = -INFINITY, l0s = 0.0f, l1s = 0.0f;

    for (int kt = 0; kt < ktiles; ++kt) {
        if (kt + 1 < ktiles) issue_tile((kt + 1) & 1, kt + 1);
        CP_COMMIT();
        CP_WAIT1();
        __syncthreads();

        const uint32_t stg = sb + (kt & 1) * STAGE_SZ;
        const bool fullmask = (kt * 64) > (qglob + w * 16 + 15);

        if (!fullmask) {
            const uint32_t km4h = stg + SK_HI + l8 * KSTRB + lg * 16;
            const uint32_t km4l = stg + SK_LO + l8 * KSTRB + lg * 16;
            const uint32_t vm4h = stg + SV_HI + l8 * VSTRB + lg * 16;
            const uint32_t vm4l = stg + SV_LO + l8 * VSTRB + lg * 16;

            // ---- S = Q K^T ----
            float Sc[8][4];
#pragma unroll
            for (int nf = 0; nf < 8; ++nf) {
                Sc[nf][0] = Sc[nf][1] = Sc[nf][2] = Sc[nf][3] = 0.0f;
                uint32_t nof = nf * 8 * KSTRB;
#pragma unroll
                for (int kf2 = 0; kf2 < 4; ++kf2) {
                    uint32_t h0, h1, h2, h3, lo0, lo1, lo2, lo3;
                    ldmx4(h0, h1, h2, h3, km4h + nof + kf2 * 64);
                    ldmx4(lo0, lo1, lo2, lo3, km4l + nof + kf2 * 64);
                    mma_bf16(Sc[nf], qhi[2 * kf2], h0, h1);
                    mma_bf16(Sc[nf], qhi[2 * kf2], lo0, lo1);
                    mma_bf16(Sc[nf], qlo[2 * kf2], h0, h1);
                    mma_bf16(Sc[nf], qhi[2 * kf2 + 1], h2, h3);
                    mma_bf16(Sc[nf], qhi[2 * kf2 + 1], lo2, lo3);
                    mma_bf16(Sc[nf], qlo[2 * kf2 + 1], h2, h3);
                }
            }

            // ---- causal mask ----
            if (kt * 64 + 63 > qglob + w * 16) {
                int cb = kt * 64 + 2 * qtr;
#pragma unroll
                for (int nf = 0; nf < 8; ++nf) {
                    int c0 = cb + nf * 8, c1 = c0 + 1;
                    if (c0 > rowg0) Sc[nf][0] = -1e30f;
                    if (c1 > rowg0) Sc[nf][1] = -1e30f;
                    if (c0 > rowg1) Sc[nf][2] = -1e30f;
                    if (c1 > rowg1) Sc[nf][3] = -1e30f;
                }
            }

            // ---- online softmax ----
            float t0 = -INFINITY, t1 = -INFINITY;
#pragma unroll
            for (int nf = 0; nf < 8; ++nf) {
                t0 = fmaxf(t0, fmaxf(Sc[nf][0], Sc[nf][1]));
                t1 = fmaxf(t1, fmaxf(Sc[nf][2], Sc[nf][3]));
            }
            t0 = fmaxf(t0, __shfl_xor_sync(0xffffffffu, t0, 1));
            t0 = fmaxf(t0, __shfl_xor_sync(0xffffffffu, t0, 2));
            t1 = fmaxf(t1, __shfl_xor_sync(0xffffffffu, t1, 1));
            t1 = fmaxf(t1, __shfl_xor_sync(0xffffffffu, t1, 2));
            float n0 = fmaxf(m0, t0), n1 = fmaxf(m1, t1);
            float c0 = __expf(m0 - n0), c1 = __expf(m1 - n1);
            m0 = n0; m1 = n1;

            float rs0 = 0.0f, rs1 = 0.0f;
#pragma unroll
            for (int nf = 0; nf < 8; ++nf) {
                Sc[nf][0] = __expf(Sc[nf][0] - n0);
                Sc[nf][1] = __expf(Sc[nf][1] - n0);
                Sc[nf][2] = __expf(Sc[nf][2] - n1);
                Sc[nf][3] = __expf(Sc[nf][3] - n1);
                rs0 += Sc[nf][0] + Sc[nf][1];
                rs1 += Sc[nf][2] + Sc[nf][3];
            }
            rs0 += __shfl_xor_sync(0xffffffffu, rs0, 1);
            rs0 += __shfl_xor_sync(0xffffffffu, rs0, 2);
            rs1 += __shfl_xor_sync(0xffffffffu, rs1, 1);
            rs1 += __shfl_xor_sync(0xffffffffu, rs1, 2);
            l0s = l0s * c0 + rs0;
            l1s = l1s * c1 + rs1;
#pragma unroll
            for (int i = 0; i < 16; ++i) {
                O[i][0] *= c0; O[i][1] *= c0;
                O[i][2] *= c1; O[i][3] *= c1;
            }

            // ---- P fragments ----
            uint32_t phi[4][4], plo[4][4];
#pragma unroll
            for (int kv = 0; kv < 4; ++kv) {
                const float* e0 = Sc[2 * kv];
                const float* e1 = Sc[2 * kv + 1];
                float src[4][2] = {{e0[0], e0[1]}, {e0[2], e0[3]},
                                   {e1[0], e1[1]}, {e1[2], e1[3]}};
#pragma unroll
                for (int j = 0; j < 4; ++j) {
                    __nv_bfloat16 h0 = __float2bfloat16_rn(src[j][0]);
                    __nv_bfloat16 h1 = __float2bfloat16_rn(src[j][1]);
                    __nv_bfloat16 l0b = __float2bfloat16_rn(src[j][0] - __bfloat162float(h0));
                    __nv_bfloat16 l1b = __float2bfloat16_rn(src[j][1] - __bfloat162float(h1));
                    phi[kv][j] = pack_bf16(h0, h1);
                    plo[kv][j] = pack_bf16(l0b, l1b);
                }
            }

            // ---- O += P V ----
#pragma unroll
            for (int nf = 0; nf < 16; ++nf) {
                uint32_t nof = nf * 8 * VSTRB;
#pragma unroll
                for (int kv2 = 0; kv2 < 2; ++kv2) {
                    uint32_t h0, h1, h2, h3, lo0, lo1, lo2, lo3;
                    ldmx4(h0, h1, h2, h3, vm4h + nof + kv2 * 64);
                    ldmx4(lo0, lo1, lo2, lo3, vm4l + nof + kv2 * 64);
                    mma_bf16(O[nf], phi[2 * kv2], h0, h1);
                    mma_bf16(O[nf], phi[2 * kv2], lo0, lo1);
                    mma_bf16(O[nf], plo[2 * kv2], h0, h1);
                    mma_bf16(O[nf], phi[2 * kv2 + 1], h2, h3);
                    mma_bf16(O[nf], phi[2 * kv2 + 1], lo2, lo3);
                    mma_bf16(O[nf], plo[2 * kv2 + 1], h2, h3);
                }
            }
        }
        __syncthreads();
    }

    // ---- epilogue ----
    const float i0 = 1.0f / l0s, i1 = 1.0f / l1s;
    float* ob0 = out + ((size_t)h * SEQ + rowg0) * DH + 2 * qtr;
    float* ob1 = out + ((size_t)h * SEQ + rowg1) * DH + 2 * qtr;
#pragma unroll
    for (int nf = 0; nf < 16; ++nf) {
        float2 a; a.x = O[nf][0] * i0; a.y = O[nf][1] * i0;
        float2 b; b.x = O[nf][2] * i1; b.y = O[nf][3] * i1;
        *(float2*)(ob0 + nf * 8) = a;
        *(float2*)(ob1 + nf * 8) = b;
    }
}

// ---------------------------------------------------------------------------
extern "C" void kernel_launch(void* const* d_in, const int* in_sizes, int n_in,
                              void* d_out, int out_size) {
    const float* q = (const float*)d_in[0];
    const float* k = (const float*)d_in[1];
    const float* v = (const float*)d_in[2];
    float* out = (float*)d_out;

    kquant_kernel<<<H * DH, 256>>>(k);
    vquant_kernel<<<H * SEQ, 128>>>(v);
    ktrans_kernel<<<dim3(SEQ / 32, DH / 32, H), dim3(32, 32)>>>();
    vtrans_kernel<<<dim3(SEQ / 32, DH / 32, H), dim3(32, 32)>>>();

    cudaFuncSetAttribute(attn_mma_kernel, cudaFuncAttributeMaxDynamicSharedMemorySize, ATTN_SMEM);
    attn_mma_kernel<<<H * 16, 256, ATTN_SMEM>>>(q, out);
}

// round 6
// speedup vs baseline: 1.4744x; 1.4744x over previous
#include <cuda_runtime.h>
#include <cuda_bf16.h>
#include <math.h>
#include <stdint.h>

#define H   32
#define SEQ 2048
#define DH  128
#define NOUT 16
#define QMAXF 7.0f

// ---------------------------------------------------------------------------
// Scratch globals
// ---------------------------------------------------------------------------
__device__ float g_vfull[(size_t)H * SEQ * DH];
__device__ __align__(16) __nv_bfloat16 g_khiT[(size_t)H * DH * SEQ];  // [h][d][s]
__device__ __align__(16) __nv_bfloat16 g_kloT[(size_t)H * DH * SEQ];
__device__ __align__(16) __nv_bfloat16 g_khi[(size_t)H * SEQ * DH];   // [h][s][d]
__device__ __align__(16) __nv_bfloat16 g_klo[(size_t)H * SEQ * DH];
__device__ __align__(16) __nv_bfloat16 g_vthi[(size_t)H * DH * SEQ];  // [h][d][s]
__device__ __align__(16) __nv_bfloat16 g_vtlo[(size_t)H * DH * SEQ];

static __device__ __forceinline__ uint32_t pack_bf16(__nv_bfloat16 a, __nv_bfloat16 b) {
    return (uint32_t)__bfloat16_as_ushort(a) | ((uint32_t)__bfloat16_as_ushort(b) << 16);
}
__device__ __forceinline__ uint32_t smem_u32(const void* p) {
    uint32_t a;
    asm("{ .reg .u64 t; cvta.to.shared.u64 t, %1; cvt.u32.u64 %0, t; }" : "=r"(a) : "l"(p));
    return a;
}
__device__ __forceinline__ void ldmx2(uint32_t& r0, uint32_t& r1, uint32_t addr) {
    asm volatile("ldmatrix.sync.aligned.m8n8.x2.shared.b16 {%0,%1}, [%2];"
                 : "=r"(r0), "=r"(r1) : "r"(addr));
}
__device__ __forceinline__ void mma_bf16(float* c, const uint32_t* a, uint32_t b0, uint32_t b1) {
    asm volatile("mma.sync.aligned.m16n8k16.row.col.f32.bf16.bf16.f32 "
                 "{%0,%1,%2,%3}, {%4,%5,%6,%7}, {%8,%9}, {%0,%1,%2,%3};"
                 : "+f"(c[0]), "+f"(c[1]), "+f"(c[2]), "+f"(c[3])
                 : "r"(a[0]), "r"(a[1]), "r"(a[2]), "r"(a[3]), "r"(b0), "r"(b1));
}

// ---------------------------------------------------------------------------
// K quantization, incremental argmax. One block per (h, d) slice.
// Writes K^T hi/lo [h][d][s] (coalesced).
// ---------------------------------------------------------------------------
__global__ __launch_bounds__(256) void kquant_kernel(const float* __restrict__ kin) {
    const int slice = blockIdx.x;
    const int h = slice >> 7;
    const int d = slice & 127;
    const int tid = threadIdx.x;
    const int lane = tid & 31, wid = tid >> 5;

    __shared__ float sval[SEQ];
    __shared__ float sabs[SEQ];      // flagged entries set to -1
    __shared__ float swv[8];
    __shared__ int   swi[8];
    __shared__ int   sgi;
    __shared__ float sgv;

    const float* base = kin + (size_t)h * SEQ * DH + d;
    float amax = -1.0f; int aidx = 0;
#pragma unroll
    for (int j = 0; j < 8; ++j) {
        int i = tid + 256 * j;
        float v = base[(size_t)i * DH];
        sval[i] = v;
        float a = fabsf(v);
        sabs[i] = a;
        if (a > amax) { amax = a; aidx = i; }
    }
    __syncthreads();

    for (int it = 0; it < NOUT; ++it) {
        float bv = amax; int bi = aidx;
#pragma unroll
        for (int o = 16; o > 0; o >>= 1) {
            float ov = __shfl_xor_sync(0xffffffffu, bv, o);
            int   oi = __shfl_xor_sync(0xffffffffu, bi, o);
            if (ov > bv || (ov == bv && oi < bi)) { bv = ov; bi = oi; }
        }
        if (lane == 0) { swv[wid] = bv; swi[wid] = bi; }
        __syncthreads();
        if (tid < 8) {
            float v2 = swv[tid]; int i2 = swi[tid];
#pragma unroll
            for (int o = 4; o > 0; o >>= 1) {
                float ov = __shfl_xor_sync(0xffu, v2, o, 8);
                int   oi = __shfl_xor_sync(0xffu, i2, o, 8);
                if (ov > v2 || (ov == v2 && oi < i2)) { v2 = ov; i2 = oi; }
            }
            if (tid == 0) sgi = i2;
        }
        __syncthreads();
        int g = sgi;
        if ((g & 255) == tid) {
            sabs[g] = -1.0f;
            amax = -1.0f; aidx = 0;
#pragma unroll
            for (int j = 0; j < 8; ++j) {
                int i = tid + 256 * j;
                float a = sabs[i];
                if (a > amax) { amax = a; aidx = i; }
            }
        }
    }

    // dense max over remaining
    {
        float bv = amax;
#pragma unroll
        for (int o = 16; o > 0; o >>= 1) bv = fmaxf(bv, __shfl_xor_sync(0xffffffffu, bv, o));
        __syncthreads();
        if (lane == 0) swv[wid] = bv;
        __syncthreads();
        if (tid == 0) {
            float mx = swv[0];
#pragma unroll
            for (int j = 1; j < 8; ++j) mx = fmaxf(mx, swv[j]);
            sgv = mx;
        }
        __syncthreads();
    }
    const float scale = fmaxf(sgv, 1e-6f) / QMAXF;

    __nv_bfloat16* khT = g_khiT + ((size_t)h * DH + d) * SEQ;
    __nv_bfloat16* klT = g_kloT + ((size_t)h * DH + d) * SEQ;
#pragma unroll
    for (int j = 0; j < 8; ++j) {
        int i = tid + 256 * j;
        float v = sval[i];
        float o;
        if (sabs[i] < 0.0f) o = v;                        // outlier, exact
        else {
            float qq = rintf(__fdiv_rn(v, scale));
            qq = fminf(fmaxf(qq, -QMAXF), QMAXF);
            o = qq * scale;
        }
        __nv_bfloat16 hi = __float2bfloat16_rn(o);
        __nv_bfloat16 lo = __float2bfloat16_rn(o - __bfloat162float(hi));
        khT[i] = hi;
        klT[i] = lo;
    }
}

// ---------------------------------------------------------------------------
// K transpose: bf16 hi/lo [h][d][s] -> [h][s][d]
// ---------------------------------------------------------------------------
__global__ void ktrans_kernel() {
    __shared__ uint32_t t[32][33];
    const int s0 = blockIdx.x * 32, d0 = blockIdx.y * 32, h = blockIdx.z;
    const int tx = threadIdx.x, ty = threadIdx.y;
    size_t ri = ((size_t)h * DH + d0 + ty) * SEQ + s0 + tx;
    t[ty][tx] = pack_bf16(g_khiT[ri], g_kloT[ri]);
    __syncthreads();
    uint32_t u = t[tx][ty];                 // (d = d0+tx, s = s0+ty)
    size_t o = ((size_t)h * SEQ + s0 + ty) * DH + d0 + tx;
    g_khi[o] = __ushort_as_bfloat16((unsigned short)(u & 0xffffu));
    g_klo[o] = __ushort_as_bfloat16((unsigned short)(u >> 16));
}

// ---------------------------------------------------------------------------
// V quantization: one 128-thread block per (h, s) row.
// ---------------------------------------------------------------------------
__global__ __launch_bounds__(128) void vquant_kernel(const float* __restrict__ vin) {
    const int row = blockIdx.x;
    const int tid = threadIdx.x;

    float v = vin[(size_t)row * DH + tid];
    float a = fabsf(v);

    __shared__ float sab[DH];
    sab[tid] = a;
    __syncthreads();

    int rank = 0;
#pragma unroll 8
    for (int j = 0; j < DH; ++j) {
        float b = sab[j];
        rank += (b > a) || (b == a && j < tid);
    }
    const bool outl = (rank < NOUT);

    float da = outl ? 0.0f : a;
#pragma unroll
    for (int o = 16; o > 0; o >>= 1) da = fmaxf(da, __shfl_xor_sync(0xffffffffu, da, o));
    __shared__ float wmax[4];
    if ((tid & 31) == 0) wmax[tid >> 5] = da;
    __syncthreads();
    float mx = fmaxf(fmaxf(wmax[0], wmax[1]), fmaxf(wmax[2], wmax[3]));
    float scale = fmaxf(mx, 1e-6f) / QMAXF;

    float o;
    if (outl) o = v;
    else {
        float qq = rintf(__fdiv_rn(v, scale));
        qq = fminf(fmaxf(qq, -QMAXF), QMAXF);
        o = qq * scale;
    }
    g_vfull[(size_t)row * DH + tid] = o;
}

// ---------------------------------------------------------------------------
// V transpose + split: fp32 [h][s][d] -> bf16 hi/lo [h][d][s]
// ---------------------------------------------------------------------------
__global__ void vtrans_kernel() {
    __shared__ float t[32][33];
    const int s0 = blockIdx.x * 32, d0 = blockIdx.y * 32, h = blockIdx.z;
    const int tx = threadIdx.x, ty = threadIdx.y;
    t[ty][tx] = g_vfull[((size_t)h * SEQ + s0 + ty) * DH + d0 + tx];
    __syncthreads();
    float v = t[tx][ty];
    __nv_bfloat16 hi = __float2bfloat16_rn(v);
    __nv_bfloat16 lo = __float2bfloat16_rn(v - __bfloat162float(hi));
    size_t o = ((size_t)h * DH + d0 + ty) * SEQ + s0 + tx;
    g_vthi[o] = hi;
    g_vtlo[o] = lo;
}

// ---------------------------------------------------------------------------
// FA2 split-bf16 mma.sync flash attention (R4-proven shape).
// Block = 128 threads (4 warps), BM = 64, BN = 64, D = 128, 71 KB smem.
// ---------------------------------------------------------------------------
#define SK_HI 0
#define SK_LO 17408
#define SV_HI 34816
#define SV_LO 53248
#define ATTN_SMEM 71680
#define KSTRB 272
#define VSTRB 144

extern __shared__ char sm_dyn[];

__global__ __launch_bounds__(128, 2)
void attn_mma_kernel(const float* __restrict__ qin, float* __restrict__ out) {
    const uint32_t sb = smem_u32(sm_dyn);
    const int tid  = threadIdx.x;
    const int w    = tid >> 5;
    const int lane = tid & 31;
    const int bx = blockIdx.x;
    const int h  = bx & 31;
    const int qt = 31 - (bx >> 5);          // heavy tiles first
    const int qglob = qt * 64;

    const int quad = lane >> 2;
    const int qtr  = lane & 3;
    const int r0 = w * 16 + quad;
    const int rowg0 = qglob + r0;
    const int rowg1 = rowg0 + 8;

    // ---- stage Q (scaled) as fp32 into smem, build A-fragments ----
    float* sQf = (float*)(sm_dyn + SV_HI);  // [64][132]
    {
        const float sms = 0.08838834764831845f;
        const float4* qbase = (const float4*)(qin + ((size_t)h * SEQ + qglob) * DH);
        for (int i = tid; i < 64 * 32; i += 128) {
            int r = i >> 5, c = i & 31;
            float4 v = qbase[r * 32 + c];
            v.x *= sms; v.y *= sms; v.z *= sms; v.w *= sms;
            *(float4*)&sQf[r * 132 + c * 4] = v;
        }
    }
    __syncthreads();

    uint32_t qhi[8][4], qlo[8][4];
    {
        const float* s0 = &sQf[r0 * 132];
        const float* s1 = &sQf[(r0 + 8) * 132];
#pragma unroll
        for (int kf = 0; kf < 8; ++kf) {
            int k0 = kf * 16 + 2 * qtr;
            float e[4][2] = {{s0[k0], s0[k0 + 1]}, {s1[k0], s1[k0 + 1]},
                             {s0[k0 + 8], s0[k0 + 9]}, {s1[k0 + 8], s1[k0 + 9]}};
#pragma unroll
            for (int j = 0; j < 4; ++j) {
                __nv_bfloat16 h0 = __float2bfloat16_rn(e[j][0]);
                __nv_bfloat16 h1 = __float2bfloat16_rn(e[j][1]);
                __nv_bfloat16 l0 = __float2bfloat16_rn(e[j][0] - __bfloat162float(h0));
                __nv_bfloat16 l1 = __float2bfloat16_rn(e[j][1] - __bfloat162float(h1));
                qhi[kf][j] = pack_bf16(h0, h1);
                qlo[kf][j] = pack_bf16(l0, l1);
            }
        }
    }
    __syncthreads();   // Q staging region will be overwritten by V tiles

    // ldmatrix base addresses (lanes 0-15 meaningful for .x2)
    const int l8 = lane & 7;
    const int lh = (lane >> 3) & 1;
    const uint32_t kmxH = sb + SK_HI + l8 * KSTRB + lh * 16;
    const uint32_t kmxL = sb + SK_LO + l8 * KSTRB + lh * 16;
    const uint32_t vmxH = sb + SV_HI + l8 * VSTRB + lh * 16;
    const uint32_t vmxL = sb + SV_LO + l8 * VSTRB + lh * 16;

    const __nv_bfloat16* khi_h = g_khi + (size_t)h * SEQ * DH;
    const __nv_bfloat16* klo_h = g_klo + (size_t)h * SEQ * DH;
    const __nv_bfloat16* vhi_h = g_vthi + (size_t)h * DH * SEQ;
    const __nv_bfloat16* vlo_h = g_vtlo + (size_t)h * DH * SEQ;

    float O[16][4];
#pragma unroll
    for (int i = 0; i < 16; ++i)
#pragma unroll
        for (int j = 0; j < 4; ++j) O[i][j] = 0.0f;
    float m0 = -INFINITY, m1 = -INFINITY, l0 = 0.0f, l1 = 0.0f;

    for (int kt = 0; kt <= qt; ++kt) {
        // ---- load K hi/lo [64][128] and V^T hi/lo [128][64] tiles ----
        {
            const uint4* kb0 = (const uint4*)(khi_h + (size_t)kt * 64 * DH);
            const uint4* kb1 = (const uint4*)(klo_h + (size_t)kt * 64 * DH);
#pragma unroll
            for (int i = tid; i < 1024; i += 128) {
                int r = i >> 4, c = i & 15;
                uint32_t sa = r * KSTRB + c * 16;
                *(uint4*)(sm_dyn + SK_HI + sa) = kb0[r * 16 + c];
                *(uint4*)(sm_dyn + SK_LO + sa) = kb1[r * 16 + c];
            }
            const __nv_bfloat16* vb0 = vhi_h + (size_t)kt * 64;
            const __nv_bfloat16* vb1 = vlo_h + (size_t)kt * 64;
#pragma unroll
            for (int i = tid; i < 1024; i += 128) {
                int r = i >> 3, c = i & 7;
                uint32_t sa = r * VSTRB + c * 16;
                *(uint4*)(sm_dyn + SV_HI + sa) = ((const uint4*)(vb0 + (size_t)r * SEQ))[c];
                *(uint4*)(sm_dyn + SV_LO + sa) = ((const uint4*)(vb1 + (size_t)r * SEQ))[c];
            }
        }
        __syncthreads();

        // ---- S = Q K^T : 8 n-frags, 8 k-frags, 3-term split ----
        float Sc[8][4];
#pragma unroll
        for (int nf = 0; nf < 8; ++nf) {
            Sc[nf][0] = Sc[nf][1] = Sc[nf][2] = Sc[nf][3] = 0.0f;
            uint32_t nof = nf * 8 * KSTRB;
#pragma unroll
            for (int kf = 0; kf < 8; ++kf) {
                uint32_t b0h, b1h, b0l, b1l;
                ldmx2(b0h, b1h, kmxH + nof + kf * 32);
                ldmx2(b0l, b1l, kmxL + nof + kf * 32);
                mma_bf16(Sc[nf], qhi[kf], b0h, b1h);
                mma_bf16(Sc[nf], qhi[kf], b0l, b1l);
                mma_bf16(Sc[nf], qlo[kf], b0h, b1h);
            }
        }

        // ---- causal mask (diagonal tile only) ----
        if (kt == qt) {
            int cb = kt * 64 + 2 * qtr;
#pragma unroll
            for (int nf = 0; nf < 8; ++nf) {
                int c0 = cb + nf * 8, c1 = c0 + 1;
                if (c0 > rowg0) Sc[nf][0] = -1e30f;
                if (c1 > rowg0) Sc[nf][1] = -1e30f;
                if (c0 > rowg1) Sc[nf][2] = -1e30f;
                if (c1 > rowg1) Sc[nf][3] = -1e30f;
            }
        }

        // ---- online softmax ----
        float t0 = -INFINITY, t1 = -INFINITY;
#pragma unroll
        for (int nf = 0; nf < 8; ++nf) {
            t0 = fmaxf(t0, fmaxf(Sc[nf][0], Sc[nf][1]));
            t1 = fmaxf(t1, fmaxf(Sc[nf][2], Sc[nf][3]));
        }
        t0 = fmaxf(t0, __shfl_xor_sync(0xffffffffu, t0, 1));
        t0 = fmaxf(t0, __shfl_xor_sync(0xffffffffu, t0, 2));
        t1 = fmaxf(t1, __shfl_xor_sync(0xffffffffu, t1, 1));
        t1 = fmaxf(t1, __shfl_xor_sync(0xffffffffu, t1, 2));
        float n0 = fmaxf(m0, t0), n1 = fmaxf(m1, t1);
        float c0 = __expf(m0 - n0), c1 = __expf(m1 - n1);
        m0 = n0; m1 = n1;

        float rs0 = 0.0f, rs1 = 0.0f;
#pragma unroll
        for (int nf = 0; nf < 8; ++nf) {
            Sc[nf][0] = __expf(Sc[nf][0] - n0);
            Sc[nf][1] = __expf(Sc[nf][1] - n0);
            Sc[nf][2] = __expf(Sc[nf][2] - n1);
            Sc[nf][3] = __expf(Sc[nf][3] - n1);
            rs0 += Sc[nf][0] + Sc[nf][1];
            rs1 += Sc[nf][2] + Sc[nf][3];
        }
        rs0 += __shfl_xor_sync(0xffffffffu, rs0, 1);
        rs0 += __shfl_xor_sync(0xffffffffu, rs0, 2);
        rs1 += __shfl_xor_sync(0xffffffffu, rs1, 1);
        rs1 += __shfl_xor_sync(0xffffffffu, rs1, 2);
        l0 = l0 * c0 + rs0;
        l1 = l1 * c1 + rs1;
#pragma unroll
        for (int i = 0; i < 16; ++i) {
            O[i][0] *= c0; O[i][1] *= c0;
            O[i][2] *= c1; O[i][3] *= c1;
        }

        // ---- P fragments (hi/lo split, built in registers) ----
        uint32_t phi[4][4], plo[4][4];
#pragma unroll
        for (int kv = 0; kv < 4; ++kv) {
            const float* e0 = Sc[2 * kv];
            const float* e1 = Sc[2 * kv + 1];
            float src[4][2] = {{e0[0], e0[1]}, {e0[2], e0[3]}, {e1[0], e1[1]}, {e1[2], e1[3]}};
#pragma unroll
            for (int j = 0; j < 4; ++j) {
                __nv_bfloat16 h0 = __float2bfloat16_rn(src[j][0]);
                __nv_bfloat16 h1 = __float2bfloat16_rn(src[j][1]);
                __nv_bfloat16 l0b = __float2bfloat16_rn(src[j][0] - __bfloat162float(h0));
                __nv_bfloat16 l1b = __float2bfloat16_rn(src[j][1] - __bfloat162float(h1));
                phi[kv][j] = pack_bf16(h0, h1);
                plo[kv][j] = pack_bf16(l0b, l1b);
            }
        }

        // ---- O += P V (V^T in smem, 16 n-frags over d, 4 k-frags over s) ----
#pragma unroll
        for (int nf = 0; nf < 16; ++nf) {
            uint32_t nof = nf * 8 * VSTRB;
#pragma unroll
            for (int kv = 0; kv < 4; ++kv) {
                uint32_t b0h, b1h, b0l, b1l;
                ldmx2(b0h, b1h, vmxH + nof + kv * 32);
                ldmx2(b0l, b1l, vmxL + nof + kv * 32);
                mma_bf16(O[nf], phi[kv], b0h, b1h);
                mma_bf16(O[nf], phi[kv], b0l, b1l);
                mma_bf16(O[nf], plo[kv], b0h, b1h);
            }
        }
        __syncthreads();
    }

    // ---- epilogue ----
    const float i0 = 1.0f / l0, i1 = 1.0f / l1;
    float* ob0 = out + ((size_t)h * SEQ + rowg0) * DH + 2 * qtr;
    float* ob1 = out + ((size_t)h * SEQ + rowg1) * DH + 2 * qtr;
#pragma unroll
    for (int nf = 0; nf < 16; ++nf) {
        float2 a; a.x = O[nf][0] * i0; a.y = O[nf][1] * i0;
        float2 b; b.x = O[nf][2] * i1; b.y = O[nf][3] * i1;
        *(float2*)(ob0 + nf * 8) = a;
        *(float2*)(ob1 + nf * 8) = b;
    }
}

// ---------------------------------------------------------------------------
extern "C" void kernel_launch(void* const* d_in, const int* in_sizes, int n_in,
                              void* d_out, int out_size) {
    const float* q = (const float*)d_in[0];
    const float* k = (const float*)d_in[1];
    const float* v = (const float*)d_in[2];
    float* out = (float*)d_out;

    kquant_kernel<<<H * DH, 256>>>(k);
    vquant_kernel<<<H * SEQ, 128>>>(v);
    ktrans_kernel<<<dim3(SEQ / 32, DH / 32, H), dim3(32, 32)>>>();
    vtrans_kernel<<<dim3(SEQ / 32, DH / 32, H), dim3(32, 32)>>>();

    cudaFuncSetAttribute(attn_mma_kernel, cudaFuncAttributeMaxDynamicSharedMemorySize, ATTN_SMEM);
    attn_mma_kernel<<<H * 32, 128, ATTN_SMEM>>>(q, out);
}

// round 7
// speedup vs baseline: 1.5226x; 1.0327x over previous
#include <cuda_runtime.h>
#include <cuda_bf16.h>
#include <math.h>
#include <stdint.h>

#define H   32
#define SEQ 2048
#define DH  128
#define NOUT 16
#define QMAXF 7.0f

// ---------------------------------------------------------------------------
// Scratch globals
// ---------------------------------------------------------------------------
__device__ float g_vfull[(size_t)H * SEQ * DH];
__device__ __align__(16) __nv_bfloat16 g_khiT[(size_t)H * DH * SEQ];  // [h][d][s]
__device__ __align__(16) __nv_bfloat16 g_kloT[(size_t)H * DH * SEQ];
__device__ __align__(16) __nv_bfloat16 g_khi[(size_t)H * SEQ * DH];   // [h][s][d]
__device__ __align__(16) __nv_bfloat16 g_klo[(size_t)H * SEQ * DH];
__device__ __align__(16) __nv_bfloat16 g_vthi[(size_t)H * DH * SEQ];  // [h][d][s]
__device__ __align__(16) __nv_bfloat16 g_vtlo[(size_t)H * DH * SEQ];

static __device__ __forceinline__ uint32_t pack_bf16(__nv_bfloat16 a, __nv_bfloat16 b) {
    return (uint32_t)__bfloat16_as_ushort(a) | ((uint32_t)__bfloat16_as_ushort(b) << 16);
}
__device__ __forceinline__ uint32_t smem_u32(const void* p) {
    uint32_t a;
    asm("{ .reg .u64 t; cvta.to.shared.u64 t, %1; cvt.u32.u64 %0, t; }" : "=r"(a) : "l"(p));
    return a;
}
__device__ __forceinline__ void ldmx4(uint32_t& r0, uint32_t& r1, uint32_t& r2, uint32_t& r3,
                                      uint32_t addr) {
    asm volatile("ldmatrix.sync.aligned.m8n8.x4.shared.b16 {%0,%1,%2,%3}, [%4];"
                 : "=r"(r0), "=r"(r1), "=r"(r2), "=r"(r3) : "r"(addr));
}
__device__ __forceinline__ void mma_bf16(float* c, const uint32_t* a, uint32_t b0, uint32_t b1) {
    asm volatile("mma.sync.aligned.m16n8k16.row.col.f32.bf16.bf16.f32 "
                 "{%0,%1,%2,%3}, {%4,%5,%6,%7}, {%8,%9}, {%0,%1,%2,%3};"
                 : "+f"(c[0]), "+f"(c[1]), "+f"(c[2]), "+f"(c[3])
                 : "r"(a[0]), "r"(a[1]), "r"(a[2]), "r"(a[3]), "r"(b0), "r"(b1));
}
#define CP_ASYNC16(dst, src) do { \
    size_t _g = __cvta_generic_to_global((const void*)(src)); \
    asm volatile("cp.async.cg.shared.global [%0], [%1], 16;" :: "r"(dst), "l"(_g) : "memory"); \
} while (0)
#define CP_COMMIT() asm volatile("cp.async.commit_group;" ::: "memory")
#define CP_WAIT0()  asm volatile("cp.async.wait_group 0;" ::: "memory")
#define CP_WAIT1()  asm volatile("cp.async.wait_group 1;" ::: "memory")

// ---------------------------------------------------------------------------
// K quantization, incremental argmax. One block per (h, d) slice.
// Writes K^T hi/lo [h][d][s] (coalesced).
// ---------------------------------------------------------------------------
__global__ __launch_bounds__(256) void kquant_kernel(const float* __restrict__ kin) {
    const int slice = blockIdx.x;
    const int h = slice >> 7;
    const int d = slice & 127;
    const int tid = threadIdx.x;
    const int lane = tid & 31, wid = tid >> 5;

    __shared__ float sval[SEQ];
    __shared__ float sabs[SEQ];      // flagged entries set to -1
    __shared__ float swv[8];
    __shared__ int   swi[8];
    __shared__ int   sgi;
    __shared__ float sgv;

    const float* base = kin + (size_t)h * SEQ * DH + d;
    float amax = -1.0f; int aidx = 0;
#pragma unroll
    for (int j = 0; j < 8; ++j) {
        int i = tid + 256 * j;
        float v = base[(size_t)i * DH];
        sval[i] = v;
        float a = fabsf(v);
        sabs[i] = a;
        if (a > amax) { amax = a; aidx = i; }
    }
    __syncthreads();

    for (int it = 0; it < NOUT; ++it) {
        float bv = amax; int bi = aidx;
#pragma unroll
        for (int o = 16; o > 0; o >>= 1) {
            float ov = __shfl_xor_sync(0xffffffffu, bv, o);
            int   oi = __shfl_xor_sync(0xffffffffu, bi, o);
            if (ov > bv || (ov == bv && oi < bi)) { bv = ov; bi = oi; }
        }
        if (lane == 0) { swv[wid] = bv; swi[wid] = bi; }
        __syncthreads();
        if (tid < 8) {
            float v2 = swv[tid]; int i2 = swi[tid];
#pragma unroll
            for (int o = 4; o > 0; o >>= 1) {
                float ov = __shfl_xor_sync(0xffu, v2, o, 8);
                int   oi = __shfl_xor_sync(0xffu, i2, o, 8);
                if (ov > v2 || (ov == v2 && oi < i2)) { v2 = ov; i2 = oi; }
            }
            if (tid == 0) sgi = i2;
        }
        __syncthreads();
        int g = sgi;
        if ((g & 255) == tid) {
            sabs[g] = -1.0f;
            amax = -1.0f; aidx = 0;
#pragma unroll
            for (int j = 0; j < 8; ++j) {
                int i = tid + 256 * j;
                float a = sabs[i];
                if (a > amax) { amax = a; aidx = i; }
            }
        }
    }

    // dense max over remaining
    {
        float bv = amax;
#pragma unroll
        for (int o = 16; o > 0; o >>= 1) bv = fmaxf(bv, __shfl_xor_sync(0xffffffffu, bv, o));
        __syncthreads();
        if (lane == 0) swv[wid] = bv;
        __syncthreads();
        if (tid == 0) {
            float mx = swv[0];
#pragma unroll
            for (int j = 1; j < 8; ++j) mx = fmaxf(mx, swv[j]);
            sgv = mx;
        }
        __syncthreads();
    }
    const float scale = fmaxf(sgv, 1e-6f) / QMAXF;

    __nv_bfloat16* khT = g_khiT + ((size_t)h * DH + d) * SEQ;
    __nv_bfloat16* klT = g_kloT + ((size_t)h * DH + d) * SEQ;
#pragma unroll
    for (int j = 0; j < 8; ++j) {
        int i = tid + 256 * j;
        float v = sval[i];
        float o;
        if (sabs[i] < 0.0f) o = v;                        // outlier, exact
        else {
            float qq = rintf(__fdiv_rn(v, scale));
            qq = fminf(fmaxf(qq, -QMAXF), QMAXF);
            o = qq * scale;
        }
        __nv_bfloat16 hi = __float2bfloat16_rn(o);
        __nv_bfloat16 lo = __float2bfloat16_rn(o - __bfloat162float(hi));
        khT[i] = hi;
        klT[i] = lo;
    }
}

// ---------------------------------------------------------------------------
// K transpose: bf16 hi/lo [h][d][s] -> [h][s][d]
// ---------------------------------------------------------------------------
__global__ void ktrans_kernel() {
    __shared__ uint32_t t[32][33];
    const int s0 = blockIdx.x * 32, d0 = blockIdx.y * 32, h = blockIdx.z;
    const int tx = threadIdx.x, ty = threadIdx.y;
    size_t ri = ((size_t)h * DH + d0 + ty) * SEQ + s0 + tx;
    t[ty][tx] = pack_bf16(g_khiT[ri], g_kloT[ri]);
    __syncthreads();
    uint32_t u = t[tx][ty];                 // (d = d0+tx, s = s0+ty)
    size_t o = ((size_t)h * SEQ + s0 + ty) * DH + d0 + tx;
    g_khi[o] = __ushort_as_bfloat16((unsigned short)(u & 0xffffu));
    g_klo[o] = __ushort_as_bfloat16((unsigned short)(u >> 16));
}

// ---------------------------------------------------------------------------
// V quantization: one 128-thread block per (h, s) row.
// ---------------------------------------------------------------------------
__global__ __launch_bounds__(128) void vquant_kernel(const float* __restrict__ vin) {
    const int row = blockIdx.x;
    const int tid = threadIdx.x;

    float v = vin[(size_t)row * DH + tid];
    float a = fabsf(v);

    __shared__ float sab[DH];
    sab[tid] = a;
    __syncthreads();

    int rank = 0;
#pragma unroll 8
    for (int j = 0; j < DH; ++j) {
        float b = sab[j];
        rank += (b > a) || (b == a && j < tid);
    }
    const bool outl = (rank < NOUT);

    float da = outl ? 0.0f : a;
#pragma unroll
    for (int o = 16; o > 0; o >>= 1) da = fmaxf(da, __shfl_xor_sync(0xffffffffu, da, o));
    __shared__ float wmax[4];
    if ((tid & 31) == 0) wmax[tid >> 5] = da;
    __syncthreads();
    float mx = fmaxf(fmaxf(wmax[0], wmax[1]), fmaxf(wmax[2], wmax[3]));
    float scale = fmaxf(mx, 1e-6f) / QMAXF;

    float o;
    if (outl) o = v;
    else {
        float qq = rintf(__fdiv_rn(v, scale));
        qq = fminf(fmaxf(qq, -QMAXF), QMAXF);
        o = qq * scale;
    }
    g_vfull[(size_t)row * DH + tid] = o;
}

// ---------------------------------------------------------------------------
// V transpose + split: fp32 [h][s][d] -> bf16 hi/lo [h][d][s]
// ---------------------------------------------------------------------------
__global__ void vtrans_kernel() {
    __shared__ float t[32][33];
    const int s0 = blockIdx.x * 32, d0 = blockIdx.y * 32, h = blockIdx.z;
    const int tx = threadIdx.x, ty = threadIdx.y;
    t[ty][tx] = g_vfull[((size_t)h * SEQ + s0 + ty) * DH + d0 + tx];
    __syncthreads();
    float v = t[tx][ty];
    __nv_bfloat16 hi = __float2bfloat16_rn(v);
    __nv_bfloat16 lo = __float2bfloat16_rn(v - __bfloat162float(hi));
    size_t o = ((size_t)h * DH + d0 + ty) * SEQ + s0 + tx;
    g_vthi[o] = hi;
    g_vtlo[o] = lo;
}

// ---------------------------------------------------------------------------
// FA2 split-bf16 mma.sync flash attention, in-place cp.async phase pipeline.
// Block = 128 threads (4 warps), BM = 64, BN = 64, D = 128, 71 KB smem,
// 2 blocks/SM. QK overlaps the V(kt) load; softmax+PV overlap the K(kt+1) load.
// ---------------------------------------------------------------------------
#define SK_HI 0
#define SK_LO 17408
#define SV_HI 34816
#define SV_LO 53248
#define ATTN_SMEM 71680
#define KSTRB 272
#define VSTRB 144

extern __shared__ char sm_dyn[];

__global__ __launch_bounds__(128, 2)
void attn_mma_kernel(const float* __restrict__ qin, float* __restrict__ out) {
    const uint32_t sb = smem_u32(sm_dyn);
    const int tid  = threadIdx.x;
    const int w    = tid >> 5;
    const int lane = tid & 31;
    const int bx = blockIdx.x;
    const int h  = bx & 31;
    const int qt = 31 - (bx >> 5);          // heavy tiles first
    const int qglob = qt * 64;

    const int quad = lane >> 2;
    const int qtr  = lane & 3;
    const int r0 = w * 16 + quad;
    const int rowg0 = qglob + r0;
    const int rowg1 = rowg0 + 8;

    const __nv_bfloat16* khi_h = g_khi + (size_t)h * SEQ * DH;
    const __nv_bfloat16* klo_h = g_klo + (size_t)h * SEQ * DH;
    const __nv_bfloat16* vhi_h = g_vthi + (size_t)h * DH * SEQ;
    const __nv_bfloat16* vlo_h = g_vtlo + (size_t)h * DH * SEQ;

    // --- async tile loaders (16 cp.async per thread each) ---
    auto issue_k = [&](int kt) {
        const uint4* kb0 = (const uint4*)(khi_h + (size_t)kt * 64 * DH);
        const uint4* kb1 = (const uint4*)(klo_h + (size_t)kt * 64 * DH);
#pragma unroll
        for (int i = tid; i < 1024; i += 128) {
            int r = i >> 4, c = i & 15;
            uint32_t sa = r * KSTRB + c * 16;
            CP_ASYNC16(sb + SK_HI + sa, kb0 + r * 16 + c);
            CP_ASYNC16(sb + SK_LO + sa, kb1 + r * 16 + c);
        }
    };
    auto issue_v = [&](int kt) {
        const __nv_bfloat16* vb0 = vhi_h + (size_t)kt * 64;
        const __nv_bfloat16* vb1 = vlo_h + (size_t)kt * 64;
#pragma unroll
        for (int i = tid; i < 1024; i += 128) {
            int r = i >> 3, c = i & 7;
            uint32_t sa = r * VSTRB + c * 16;
            CP_ASYNC16(sb + SV_HI + sa, (const uint4*)(vb0 + (size_t)r * SEQ) + c);
            CP_ASYNC16(sb + SV_LO + sa, (const uint4*)(vb1 + (size_t)r * SEQ) + c);
        }
    };

    // prologue: K(0) in flight while we stage Q
    issue_k(0);
    CP_COMMIT();

    // ---- stage Q (scaled) as fp32 into the V region, build A-fragments ----
    float* sQf = (float*)(sm_dyn + SV_HI);  // [64][132]
    {
        const float sms = 0.08838834764831845f;
        const float4* qbase = (const float4*)(qin + ((size_t)h * SEQ + qglob) * DH);
        for (int i = tid; i < 64 * 32; i += 128) {
            int r = i >> 5, c = i & 31;
            float4 v = qbase[r * 32 + c];
            v.x *= sms; v.y *= sms; v.z *= sms; v.w *= sms;
            *(float4*)&sQf[r * 132 + c * 4] = v;
        }
    }
    __syncthreads();

    uint32_t qhi[8][4], qlo[8][4];
    {
        const float* s0 = &sQf[r0 * 132];
        const float* s1 = &sQf[(r0 + 8) * 132];
#pragma unroll
        for (int kf = 0; kf < 8; ++kf) {
            int k0 = kf * 16 + 2 * qtr;
            float e[4][2] = {{s0[k0], s0[k0 + 1]}, {s1[k0], s1[k0 + 1]},
                             {s0[k0 + 8], s0[k0 + 9]}, {s1[k0 + 8], s1[k0 + 9]}};
#pragma unroll
            for (int j = 0; j < 4; ++j) {
                __nv_bfloat16 h0 = __float2bfloat16_rn(e[j][0]);
                __nv_bfloat16 h1 = __float2bfloat16_rn(e[j][1]);
                __nv_bfloat16 l0 = __float2bfloat16_rn(e[j][0] - __bfloat162float(h0));
                __nv_bfloat16 l1 = __float2bfloat16_rn(e[j][1] - __bfloat162float(h1));
                qhi[kf][j] = pack_bf16(h0, h1);
                qlo[kf][j] = pack_bf16(l0, l1);
            }
        }
    }
    __syncthreads();   // Q staging done; V region may now be overwritten

    // ldmatrix.x4 base addresses: 4 consecutive 8x8 matrices along k
    const int l8 = lane & 7;
    const int lg = (lane >> 3) & 3;
    const uint32_t km4h = sb + SK_HI + l8 * KSTRB + lg * 16;
    const uint32_t km4l = sb + SK_LO + l8 * KSTRB + lg * 16;
    const uint32_t vm4h = sb + SV_HI + l8 * VSTRB + lg * 16;
    const uint32_t vm4l = sb + SV_LO + l8 * VSTRB + lg * 16;

    float O[16][4];
#pragma unroll
    for (int i = 0; i < 16; ++i)
#pragma unroll
        for (int j = 0; j < 4; ++j) O[i][j] = 0.0f;
    float m0 = -INFINITY, m1 = -INFINITY, l0 = 0.0f, l1 = 0.0f;

    for (int kt = 0; kt <= qt; ++kt) {
        // V(kt) underway while we run QK on K(kt)
        issue_v(kt);
        CP_COMMIT();
        CP_WAIT1();            // K(kt) complete; V(kt) still in flight
        __syncthreads();

        // ---- S = Q K^T : 8 n-frags, 4 x4-loads over k, 3-term split ----
        float Sc[8][4];
#pragma unroll
        for (int nf = 0; nf < 8; ++nf) {
            Sc[nf][0] = Sc[nf][1] = Sc[nf][2] = Sc[nf][3] = 0.0f;
            uint32_t nof = nf * 8 * KSTRB;
#pragma unroll
            for (int kf2 = 0; kf2 < 4; ++kf2) {
                uint32_t h0, h1, h2, h3, lo0, lo1, lo2, lo3;
                ldmx4(h0, h1, h2, h3, km4h + nof + kf2 * 64);
                ldmx4(lo0, lo1, lo2, lo3, km4l + nof + kf2 * 64);
                mma_bf16(Sc[nf], qhi[2 * kf2], h0, h1);
                mma_bf16(Sc[nf], qhi[2 * kf2], lo0, lo1);
                mma_bf16(Sc[nf], qlo[2 * kf2], h0, h1);
                mma_bf16(Sc[nf], qhi[2 * kf2 + 1], h2, h3);
                mma_bf16(Sc[nf], qhi[2 * kf2 + 1], lo2, lo3);
                mma_bf16(Sc[nf], qlo[2 * kf2 + 1], h2, h3);
            }
        }

        CP_WAIT0();            // V(kt) complete
        __syncthreads();       // all warps done reading K(kt) -> K region free

        // K(kt+1) underway while we run softmax + PV on V(kt)
        if (kt < qt) {
            issue_k(kt + 1);
            CP_COMMIT();
        }

        // ---- causal mask (diagonal tile only) ----
        if (kt == qt) {
            int cb = kt * 64 + 2 * qtr;
#pragma unroll
            for (int nf = 0; nf < 8; ++nf) {
                int c0 = cb + nf * 8, c1 = c0 + 1;
                if (c0 > rowg0) Sc[nf][0] = -1e30f;
                if (c1 > rowg0) Sc[nf][1] = -1e30f;
                if (c0 > rowg1) Sc[nf][2] = -1e30f;
                if (c1 > rowg1) Sc[nf][3] = -1e30f;
            }
        }

        // ---- online softmax ----
        float t0 = -INFINITY, t1 = -INFINITY;
#pragma unroll
        for (int nf = 0; nf < 8; ++nf) {
            t0 = fmaxf(t0, fmaxf(Sc[nf][0], Sc[nf][1]));
            t1 = fmaxf(t1, fmaxf(Sc[nf][2], Sc[nf][3]));
        }
        t0 = fmaxf(t0, __shfl_xor_sync(0xffffffffu, t0, 1));
        t0 = fmaxf(t0, __shfl_xor_sync(0xffffffffu, t0, 2));
        t1 = fmaxf(t1, __shfl_xor_sync(0xffffffffu, t1, 1));
        t1 = fmaxf(t1, __shfl_xor_sync(0xffffffffu, t1, 2));
        float n0 = fmaxf(m0, t0), n1 = fmaxf(m1, t1);
        float c0 = __expf(m0 - n0), c1 = __expf(m1 - n1);
        m0 = n0; m1 = n1;

        float rs0 = 0.0f, rs1 = 0.0f;
#pragma unroll
        for (int nf = 0; nf < 8; ++nf) {
            Sc[nf][0] = __expf(Sc[nf][0] - n0);
            Sc[nf][1] = __expf(Sc[nf][1] - n0);
            Sc[nf][2] = __expf(Sc[nf][2] - n1);
            Sc[nf][3] = __expf(Sc[nf][3] - n1);
            rs0 += Sc[nf][0] + Sc[nf][1];
            rs1 += Sc[nf][2] + Sc[nf][3];
        }
        rs0 += __shfl_xor_sync(0xffffffffu, rs0, 1);
        rs0 += __shfl_xor_sync(0xffffffffu, rs0, 2);
        rs1 += __shfl_xor_sync(0xffffffffu, rs1, 1);
        rs1 += __shfl_xor_sync(0xffffffffu, rs1, 2);
        l0 = l0 * c0 + rs0;
        l1 = l1 * c1 + rs1;
#pragma unroll
        for (int i = 0; i < 16; ++i) {
            O[i][0] *= c0; O[i][1] *= c0;
            O[i][2] *= c1; O[i][3] *= c1;
        }

        // ---- P fragments (hi/lo split, built in registers) ----
        uint32_t phi[4][4], plo[4][4];
#pragma unroll
        for (int kv = 0; kv < 4; ++kv) {
            const float* e0 = Sc[2 * kv];
            const float* e1 = Sc[2 * kv + 1];
            float src[4][2] = {{e0[0], e0[1]}, {e0[2], e0[3]}, {e1[0], e1[1]}, {e1[2], e1[3]}};
#pragma unroll
            for (int j = 0; j < 4; ++j) {
                __nv_bfloat16 h0 = __float2bfloat16_rn(src[j][0]);
                __nv_bfloat16 h1 = __float2bfloat16_rn(src[j][1]);
                __nv_bfloat16 l0b = __float2bfloat16_rn(src[j][0] - __bfloat162float(h0));
                __nv_bfloat16 l1b = __float2bfloat16_rn(src[j][1] - __bfloat162float(h1));
                phi[kv][j] = pack_bf16(h0, h1);
                plo[kv][j] = pack_bf16(l0b, l1b);
            }
        }

        // ---- O += P V (V^T in smem, 16 n-frags over d, 2 x4-loads over s) ----
#pragma unroll
        for (int nf = 0; nf < 16; ++nf) {
            uint32_t nof = nf * 8 * VSTRB;
#pragma unroll
            for (int kv2 = 0; kv2 < 2; ++kv2) {
                uint32_t h0, h1, h2, h3, lo0, lo1, lo2, lo3;
                ldmx4(h0, h1, h2, h3, vm4h + nof + kv2 * 64);
                ldmx4(lo0, lo1, lo2, lo3, vm4l + nof + kv2 * 64);
                mma_bf16(O[nf], phi[2 * kv2], h0, h1);
                mma_bf16(O[nf], phi[2 * kv2], lo0, lo1);
                mma_bf16(O[nf], plo[2 * kv2], h0, h1);
                mma_bf16(O[nf], phi[2 * kv2 + 1], h2, h3);
                mma_bf16(O[nf], phi[2 * kv2 + 1], lo2, lo3);
                mma_bf16(O[nf], plo[2 * kv2 + 1], h2, h3);
            }
        }
        __syncthreads();       // all warps done reading V(kt) before next issue_v
    }

    // ---- epilogue ----
    const float i0 = 1.0f / l0, i1 = 1.0f / l1;
    float* ob0 = out + ((size_t)h * SEQ + rowg0) * DH + 2 * qtr;
    float* ob1 = out + ((size_t)h * SEQ + rowg1) * DH + 2 * qtr;
#pragma unroll
    for (int nf = 0; nf < 16; ++nf) {
        float2 a; a.x = O[nf][0] * i0; a.y = O[nf][1] * i0;
        float2 b; b.x = O[nf][2] * i1; b.y = O[nf][3] * i1;
        *(float2*)(ob0 + nf * 8) = a;
        *(float2*)(ob1 + nf * 8) = b;
    }
}

// ---------------------------------------------------------------------------
extern "C" void kernel_launch(void* const* d_in, const int* in_sizes, int n_in,
                              void* d_out, int out_size) {
    const float* q = (const float*)d_in[0];
    const float* k = (const float*)d_in[1];
    const float* v = (const float*)d_in[2];
    float* out = (float*)d_out;

    kquant_kernel<<<H * DH, 256>>>(k);
    vquant_kernel<<<H * SEQ, 128>>>(v);
    ktrans_kernel<<<dim3(SEQ / 32, DH / 32, H), dim3(32, 32)>>>();
    vtrans_kernel<<<dim3(SEQ / 32, DH / 32, H), dim3(32, 32)>>>();

    cudaFuncSetAttribute(attn_mma_kernel, cudaFuncAttributeMaxDynamicSharedMemorySize, ATTN_SMEM);
    attn_mma_kernel<<<H * 32, 128, ATTN_SMEM>>>(q, out);
}

// round 8
// speedup vs baseline: 1.6890x; 1.1093x over previous
#include <cuda_runtime.h>
#include <cuda_bf16.h>
#include <math.h>
#include <stdint.h>

#define H   32
#define SEQ 2048
#define DH  128
#define NOUT 16
#define QMAXF 7.0f

// ---------------------------------------------------------------------------
// Scratch globals (K^T hi/lo in [h][d][s]; V hi/lo in [h][s][d])
// ---------------------------------------------------------------------------
__device__ __align__(16) __nv_bfloat16 g_khiT[(size_t)H * DH * SEQ];
__device__ __align__(16) __nv_bfloat16 g_kloT[(size_t)H * DH * SEQ];
__device__ __align__(16) __nv_bfloat16 g_vhi[(size_t)H * SEQ * DH];
__device__ __align__(16) __nv_bfloat16 g_vlo[(size_t)H * SEQ * DH];

static __device__ __forceinline__ uint32_t pack_bf16(__nv_bfloat16 a, __nv_bfloat16 b) {
    return (uint32_t)__bfloat16_as_ushort(a) | ((uint32_t)__bfloat16_as_ushort(b) << 16);
}
// packed bf16x2 = {lo=a, hi=b}, round-nearest-even (same as __float2bfloat16_rn)
__device__ __forceinline__ uint32_t cvtpack(float a, float b) {
    uint32_t r;
    asm("cvt.rn.bf16x2.f32 %0, %2, %1;" : "=r"(r) : "f"(a), "f"(b));
    return r;
}
__device__ __forceinline__ float2 unpack_bf(uint32_t u) {
    __nv_bfloat162 t;
    *reinterpret_cast<uint32_t*>(&t) = u;
    return __bfloat1622float2(t);
}
__device__ __forceinline__ uint32_t smem_u32(const void* p) {
    uint32_t a;
    asm("{ .reg .u64 t; cvta.to.shared.u64 t, %1; cvt.u32.u64 %0, t; }" : "=r"(a) : "l"(p));
    return a;
}
// transposed ldmatrix: B operand from [k][n]-major smem
__device__ __forceinline__ void ldmx4t(uint32_t& r0, uint32_t& r1, uint32_t& r2, uint32_t& r3,
                                       uint32_t addr) {
    asm volatile("ldmatrix.sync.aligned.m8n8.x4.trans.shared.b16 {%0,%1,%2,%3}, [%4];"
                 : "=r"(r0), "=r"(r1), "=r"(r2), "=r"(r3) : "r"(addr));
}
__device__ __forceinline__ void mma_bf16(float* c, const uint32_t* a, uint32_t b0, uint32_t b1) {
    asm volatile("mma.sync.aligned.m16n8k16.row.col.f32.bf16.bf16.f32 "
                 "{%0,%1,%2,%3}, {%4,%5,%6,%7}, {%8,%9}, {%0,%1,%2,%3};"
                 : "+f"(c[0]), "+f"(c[1]), "+f"(c[2]), "+f"(c[3])
                 : "r"(a[0]), "r"(a[1]), "r"(a[2]), "r"(a[3]), "r"(b0), "r"(b1));
}
#define CP_ASYNC16(dst, src) do { \
    size_t _g = __cvta_generic_to_global((const void*)(src)); \
    asm volatile("cp.async.cg.shared.global [%0], [%1], 16;" :: "r"(dst), "l"(_g) : "memory"); \
} while (0)
#define CP_COMMIT() asm volatile("cp.async.commit_group;" ::: "memory")
#define CP_WAIT0()  asm volatile("cp.async.wait_group 0;" ::: "memory")
#define CP_WAIT1()  asm volatile("cp.async.wait_group 1;" ::: "memory")

// ---------------------------------------------------------------------------
// K quantization, incremental argmax. One block per (h, d) slice.
// Writes K^T hi/lo [h][d][s] (coalesced) — consumed directly by attention.
// ---------------------------------------------------------------------------
__global__ __launch_bounds__(256) void kquant_kernel(const float* __restrict__ kin) {
    const int slice = blockIdx.x;
    const int h = slice >> 7;
    const int d = slice & 127;
    const int tid = threadIdx.x;
    const int lane = tid & 31, wid = tid >> 5;

    __shared__ float sval[SEQ];
    __shared__ float sabs[SEQ];      // flagged entries set to -1
    __shared__ float swv[8];
    __shared__ int   swi[8];
    __shared__ int   sgi;
    __shared__ float sgv;

    const float* base = kin + (size_t)h * SEQ * DH + d;
    float amax = -1.0f; int aidx = 0;
#pragma unroll
    for (int j = 0; j < 8; ++j) {
        int i = tid + 256 * j;
        float v = base[(size_t)i * DH];
        sval[i] = v;
        float a = fabsf(v);
        sabs[i] = a;
        if (a > amax) { amax = a; aidx = i; }
    }
    __syncthreads();

    for (int it = 0; it < NOUT; ++it) {
        float bv = amax; int bi = aidx;
#pragma unroll
        for (int o = 16; o > 0; o >>= 1) {
            float ov = __shfl_xor_sync(0xffffffffu, bv, o);
            int   oi = __shfl_xor_sync(0xffffffffu, bi, o);
            if (ov > bv || (ov == bv && oi < bi)) { bv = ov; bi = oi; }
        }
        if (lane == 0) { swv[wid] = bv; swi[wid] = bi; }
        __syncthreads();
        if (tid < 8) {
            float v2 = swv[tid]; int i2 = swi[tid];
#pragma unroll
            for (int o = 4; o > 0; o >>= 1) {
                float ov = __shfl_xor_sync(0xffu, v2, o, 8);
                int   oi = __shfl_xor_sync(0xffu, i2, o, 8);
                if (ov > v2 || (ov == v2 && oi < i2)) { v2 = ov; i2 = oi; }
            }
            if (tid == 0) sgi = i2;
        }
        __syncthreads();
        int g = sgi;
        if ((g & 255) == tid) {
            sabs[g] = -1.0f;
            amax = -1.0f; aidx = 0;
#pragma unroll
            for (int j = 0; j < 8; ++j) {
                int i = tid + 256 * j;
                float a = sabs[i];
                if (a > amax) { amax = a; aidx = i; }
            }
        }
    }

    // dense max over remaining
    {
        float bv = amax;
#pragma unroll
        for (int o = 16; o > 0; o >>= 1) bv = fmaxf(bv, __shfl_xor_sync(0xffffffffu, bv, o));
        __syncthreads();
        if (lane == 0) swv[wid] = bv;
        __syncthreads();
        if (tid == 0) {
            float mx = swv[0];
#pragma unroll
            for (int j = 1; j < 8; ++j) mx = fmaxf(mx, swv[j]);
            sgv = mx;
        }
        __syncthreads();
    }
    const float scale = fmaxf(sgv, 1e-6f) / QMAXF;

    __nv_bfloat16* khT = g_khiT + ((size_t)h * DH + d) * SEQ;
    __nv_bfloat16* klT = g_kloT + ((size_t)h * DH + d) * SEQ;
#pragma unroll
    for (int j = 0; j < 8; ++j) {
        int i = tid + 256 * j;
        float v = sval[i];
        float o;
        if (sabs[i] < 0.0f) o = v;                        // outlier, exact
        else {
            float qq = rintf(__fdiv_rn(v, scale));
            qq = fminf(fmaxf(qq, -QMAXF), QMAXF);
            o = qq * scale;
        }
        __nv_bfloat16 hi = __float2bfloat16_rn(o);
        __nv_bfloat16 lo = __float2bfloat16_rn(o - __bfloat162float(hi));
        khT[i] = hi;
        klT[i] = lo;
    }
}

// ---------------------------------------------------------------------------
// V quantization + bf16 split, fused. One 128-thread block per (h, s) row.
// Writes V hi/lo [h][s][d] (coalesced) — consumed directly by attention.
// ---------------------------------------------------------------------------
__global__ __launch_bounds__(128) void vquant_kernel(const float* __restrict__ vin) {
    const int row = blockIdx.x;
    const int tid = threadIdx.x;

    float v = vin[(size_t)row * DH + tid];
    float a = fabsf(v);

    __shared__ float sab[DH];
    sab[tid] = a;
    __syncthreads();

    int rank = 0;
#pragma unroll 8
    for (int j = 0; j < DH; ++j) {
        float b = sab[j];
        rank += (b > a) || (b == a && j < tid);
    }
    const bool outl = (rank < NOUT);

    float da = outl ? 0.0f : a;
#pragma unroll
    for (int o = 16; o > 0; o >>= 1) da = fmaxf(da, __shfl_xor_sync(0xffffffffu, da, o));
    __shared__ float wmax[4];
    if ((tid & 31) == 0) wmax[tid >> 5] = da;
    __syncthreads();
    float mx = fmaxf(fmaxf(wmax[0], wmax[1]), fmaxf(wmax[2], wmax[3]));
    float scale = fmaxf(mx, 1e-6f) / QMAXF;

    float o;
    if (outl) o = v;
    else {
        float qq = rintf(__fdiv_rn(v, scale));
        qq = fminf(fmaxf(qq, -QMAXF), QMAXF);
        o = qq * scale;
    }
    __nv_bfloat16 hi = __float2bfloat16_rn(o);
    __nv_bfloat16 lo = __float2bfloat16_rn(o - __bfloat162float(hi));
    g_vhi[(size_t)row * DH + tid] = hi;
    g_vlo[(size_t)row * DH + tid] = lo;
}

// ---------------------------------------------------------------------------
// FA2 split-bf16 mma.sync flash attention; B operands via ldmatrix.x4.trans.
// Block = 128 threads (4 warps), BM = 64, BN = 64, D = 128, 71680 B smem,
// 2 blocks/SM. In-place cp.async phase pipeline (K under PV, V under QK).
// smem: sKT hi/lo [128 d][144B] @0/@18432;  sV hi/lo [64 s][272B] @36864/@54272
// ---------------------------------------------------------------------------
#define SKT_HI 0
#define SKT_LO 18432
#define SV_HI  36864
#define SV_LO  54272
#define ATTN_SMEM 71680
#define KTSTR 144
#define VSTR  272

extern __shared__ char sm_dyn[];

__global__ __launch_bounds__(128, 2)
void attn_mma_kernel(const float* __restrict__ qin, float* __restrict__ out) {
    const uint32_t sb = smem_u32(sm_dyn);
    const int tid  = threadIdx.x;
    const int w    = tid >> 5;
    const int lane = tid & 31;
    const int bx = blockIdx.x;
    const int h  = bx & 31;
    const int qt = 31 - (bx >> 5);          // heavy tiles first
    const int qglob = qt * 64;

    const int quad = lane >> 2;
    const int qtr  = lane & 3;
    const int r0 = w * 16 + quad;
    const int rowg0 = qglob + r0;
    const int rowg1 = rowg0 + 8;

    const __nv_bfloat16* khi_h = g_khiT + (size_t)h * DH * SEQ;  // [d][s]
    const __nv_bfloat16* klo_h = g_kloT + (size_t)h * DH * SEQ;
    const __nv_bfloat16* vhi_h = g_vhi + (size_t)h * SEQ * DH;   // [s][d]
    const __nv_bfloat16* vlo_h = g_vlo + (size_t)h * SEQ * DH;

    // --- async tile loaders (16 cp.async per thread each) ---
    auto issue_k = [&](int kt) {   // K^T tile: 128 d-rows x 64 s (128B data/row)
        const __nv_bfloat16* kb0 = khi_h + (size_t)kt * 64;
        const __nv_bfloat16* kb1 = klo_h + (size_t)kt * 64;
#pragma unroll
        for (int i = tid; i < 1024; i += 128) {
            int r = i >> 3, c = i & 7;
            uint32_t sa = r * KTSTR + c * 16;
            CP_ASYNC16(sb + SKT_HI + sa, (const uint4*)(kb0 + (size_t)r * SEQ) + c);
            CP_ASYNC16(sb + SKT_LO + sa, (const uint4*)(kb1 + (size_t)r * SEQ) + c);
        }
    };
    auto issue_v = [&](int kt) {   // V tile: 64 s-rows x 128 d (256B data/row)
        const uint4* vb0 = (const uint4*)(vhi_h + (size_t)kt * 64 * DH);
        const uint4* vb1 = (const uint4*)(vlo_h + (size_t)kt * 64 * DH);
#pragma unroll
        for (int i = tid; i < 1024; i += 128) {
            int r = i >> 4, c = i & 15;
            uint32_t sa = r * VSTR + c * 16;
            CP_ASYNC16(sb + SV_HI + sa, vb0 + r * 16 + c);
            CP_ASYNC16(sb + SV_LO + sa, vb1 + r * 16 + c);
        }
    };

    // prologue: K(0) in flight while we stage Q
    issue_k(0);
    CP_COMMIT();

    // ---- stage Q (scaled) fp32 into the V region, build A-fragments ----
    float* sQf = (float*)(sm_dyn + SV_HI);  // [64][132], 33792 B <= 34816
    {
        const float sms = 0.08838834764831845f;
        const float4* qbase = (const float4*)(qin + ((size_t)h * SEQ + qglob) * DH);
        for (int i = tid; i < 64 * 32; i += 128) {
            int r = i >> 5, c = i & 31;
            float4 v = qbase[r * 32 + c];
            v.x *= sms; v.y *= sms; v.z *= sms; v.w *= sms;
            *(float4*)&sQf[r * 132 + c * 4] = v;
        }
    }
    __syncthreads();

    uint32_t qhi[8][4], qlo[8][4];
    {
        const float* s0 = &sQf[r0 * 132];
        const float* s1 = &sQf[(r0 + 8) * 132];
#pragma unroll
        for (int kf = 0; kf < 8; ++kf) {
            int k0 = kf * 16 + 2 * qtr;
            float e[4][2] = {{s0[k0], s0[k0 + 1]}, {s1[k0], s1[k0 + 1]},
                             {s0[k0 + 8], s0[k0 + 9]}, {s1[k0 + 8], s1[k0 + 9]}};
#pragma unroll
            for (int j = 0; j < 4; ++j) {
                uint32_t hp = cvtpack(e[j][0], e[j][1]);
                float2 hf = unpack_bf(hp);
                qhi[kf][j] = hp;
                qlo[kf][j] = cvtpack(e[j][0] - hf.x, e[j][1] - hf.y);
            }
        }
    }
    __syncthreads();   // Q staging done; V region may now be overwritten

    // trans-ldmatrix bases: lane l reads row (k-window + l) of the [k][n] tile
    const uint32_t kmt_h = sb + SKT_HI + lane * KTSTR;
    const uint32_t kmt_l = sb + SKT_LO + lane * KTSTR;
    const uint32_t vmt_h = sb + SV_HI + lane * VSTR;
    const uint32_t vmt_l = sb + SV_LO + lane * VSTR;

    float O[16][4];
#pragma unroll
    for (int i = 0; i < 16; ++i)
#pragma unroll
        for (int j = 0; j < 4; ++j) O[i][j] = 0.0f;
    float m0 = -INFINITY, m1 = -INFINITY, l0 = 0.0f, l1 = 0.0f;

    for (int kt = 0; kt <= qt; ++kt) {
        // V(kt) underway while we run QK on K(kt)
        issue_v(kt);
        CP_COMMIT();
        CP_WAIT1();            // K(kt) complete; V(kt) still in flight
        __syncthreads();

        // ---- S = Q K^T : 8 n-frags, 4 k-windows of 32, 3-term split ----
        float Sc[8][4];
#pragma unroll
        for (int nf = 0; nf < 8; ++nf) {
            Sc[nf][0] = Sc[nf][1] = Sc[nf][2] = Sc[nf][3] = 0.0f;
            uint32_t nof = nf * 16;                       // n-block byte offset
#pragma unroll
            for (int kf2 = 0; kf2 < 4; ++kf2) {
                uint32_t koff = kf2 * 32 * KTSTR;
                uint32_t h0, h1, h2, h3, lo0, lo1, lo2, lo3;
                ldmx4t(h0, h1, h2, h3, kmt_h + koff + nof);
                ldmx4t(lo0, lo1, lo2, lo3, kmt_l + koff + nof);
                mma_bf16(Sc[nf], qhi[2 * kf2], h0, h1);
                mma_bf16(Sc[nf], qhi[2 * kf2], lo0, lo1);
                mma_bf16(Sc[nf], qlo[2 * kf2], h0, h1);
                mma_bf16(Sc[nf], qhi[2 * kf2 + 1], h2, h3);
                mma_bf16(Sc[nf], qhi[2 * kf2 + 1], lo2, lo3);
                mma_bf16(Sc[nf], qlo[2 * kf2 + 1], h2, h3);
            }
        }

        CP_WAIT0();            // V(kt) complete
        __syncthreads();       // all warps done reading K(kt) -> K region free

        // K(kt+1) underway while we run softmax + PV on V(kt)
        if (kt < qt) {
            issue_k(kt + 1);
            CP_COMMIT();
        }

        // ---- causal mask (diagonal tile only) ----
        if (kt == qt) {
            int cb = kt * 64 + 2 * qtr;
#pragma unroll
            for (int nf = 0; nf < 8; ++nf) {
                int c0 = cb + nf * 8, c1 = c0 + 1;
                if (c0 > rowg0) Sc[nf][0] = -1e30f;
                if (c1 > rowg0) Sc[nf][1] = -1e30f;
                if (c0 > rowg1) Sc[nf][2] = -1e30f;
                if (c1 > rowg1) Sc[nf][3] = -1e30f;
            }
        }

        // ---- online softmax ----
        float t0 = -INFINITY, t1 = -INFINITY;
#pragma unroll
        for (int nf = 0; nf < 8; ++nf) {
            t0 = fmaxf(t0, fmaxf(Sc[nf][0], Sc[nf][1]));
            t1 = fmaxf(t1, fmaxf(Sc[nf][2], Sc[nf][3]));
        }
        t0 = fmaxf(t0, __shfl_xor_sync(0xffffffffu, t0, 1));
        t0 = fmaxf(t0, __shfl_xor_sync(0xffffffffu, t0, 2));
        t1 = fmaxf(t1, __shfl_xor_sync(0xffffffffu, t1, 1));
        t1 = fmaxf(t1, __shfl_xor_sync(0xffffffffu, t1, 2));
        float n0 = fmaxf(m0, t0), n1 = fmaxf(m1, t1);
        float c0 = __expf(m0 - n0), c1 = __expf(m1 - n1);
        m0 = n0; m1 = n1;

        float rs0 = 0.0f, rs1 = 0.0f;
#pragma unroll
        for (int nf = 0; nf < 8; ++nf) {
            Sc[nf][0] = __expf(Sc[nf][0] - n0);
            Sc[nf][1] = __expf(Sc[nf][1] - n0);
            Sc[nf][2] = __expf(Sc[nf][2] - n1);
            Sc[nf][3] = __expf(Sc[nf][3] - n1);
            rs0 += Sc[nf][0] + Sc[nf][1];
            rs1 += Sc[nf][2] + Sc[nf][3];
        }
        rs0 += __shfl_xor_sync(0xffffffffu, rs0, 1);
        rs0 += __shfl_xor_sync(0xffffffffu, rs0, 2);
        rs1 += __shfl_xor_sync(0xffffffffu, rs1, 1);
        rs1 += __shfl_xor_sync(0xffffffffu, rs1, 2);
        l0 = l0 * c0 + rs0;
        l1 = l1 * c1 + rs1;
#pragma unroll
        for (int i = 0; i < 16; ++i) {
            O[i][0] *= c0; O[i][1] *= c0;
            O[i][2] *= c1; O[i][3] *= c1;
        }

        // ---- P fragments (hi/lo split, packed cvt) ----
        uint32_t phi[4][4], plo[4][4];
#pragma unroll
        for (int kv = 0; kv < 4; ++kv) {
            const float* e0 = Sc[2 * kv];
            const float* e1 = Sc[2 * kv + 1];
            float src[4][2] = {{e0[0], e0[1]}, {e0[2], e0[3]}, {e1[0], e1[1]}, {e1[2], e1[3]}};
#pragma unroll
            for (int j = 0; j < 4; ++j) {
                uint32_t hp = cvtpack(src[j][0], src[j][1]);
                float2 hf = unpack_bf(hp);
                phi[kv][j] = hp;
                plo[kv][j] = cvtpack(src[j][0] - hf.x, src[j][1] - hf.y);
            }
        }

        // ---- O += P V : 16 n-frags over d, 2 k-windows of 32 over s ----
#pragma unroll
        for (int nf = 0; nf < 16; ++nf) {
            uint32_t nof = nf * 16;
#pragma unroll
            for (int kv2 = 0; kv2 < 2; ++kv2) {
                uint32_t koff = kv2 * 32 * VSTR;
                uint32_t h0, h1, h2, h3, lo0, lo1, lo2, lo3;
                ldmx4t(h0, h1, h2, h3, vmt_h + koff + nof);
                ldmx4t(lo0, lo1, lo2, lo3, vmt_l + koff + nof);
                mma_bf16(O[nf], phi[2 * kv2], h0, h1);
                mma_bf16(O[nf], phi[2 * kv2], lo0, lo1);
                mma_bf16(O[nf], plo[2 * kv2], h0, h1);
                mma_bf16(O[nf], phi[2 * kv2 + 1], h2, h3);
                mma_bf16(O[nf], phi[2 * kv2 + 1], lo2, lo3);
                mma_bf16(O[nf], plo[2 * kv2 + 1], h2, h3);
            }
        }
        __syncthreads();       // all warps done reading V(kt) before next issue_v
    }

    // ---- epilogue ----
    const float i0 = 1.0f / l0, i1 = 1.0f / l1;
    float* ob0 = out + ((size_t)h * SEQ + rowg0) * DH + 2 * qtr;
    float* ob1 = out + ((size_t)h * SEQ + rowg1) * DH + 2 * qtr;
#pragma unroll
    for (int nf = 0; nf < 16; ++nf) {
        float2 a; a.x = O[nf][0] * i0; a.y = O[nf][1] * i0;
        float2 b; b.x = O[nf][2] * i1; b.y = O[nf][3] * i1;
        *(float2*)(ob0 + nf * 8) = a;
        *(float2*)(ob1 + nf * 8) = b;
    }
}

// ---------------------------------------------------------------------------
extern "C" void kernel_launch(void* const* d_in, const int* in_sizes, int n_in,
                              void* d_out, int out_size) {
    const float* q = (const float*)d_in[0];
    const float* k = (const float*)d_in[1];
    const float* v = (const float*)d_in[2];
    float* out = (float*)d_out;

    kquant_kernel<<<H * DH, 256>>>(k);
    vquant_kernel<<<H * SEQ, 128>>>(v);

    cudaFuncSetAttribute(attn_mma_kernel, cudaFuncAttributeMaxDynamicSharedMemorySize, ATTN_SMEM);
    attn_mma_kernel<<<H * 32, 128, ATTN_SMEM>>>(q, out);
}

// round 9
// speedup vs baseline: 1.7208x; 1.0188x over previous
#include <cuda_runtime.h>
#include <cuda_bf16.h>
#include <math.h>
#include <stdint.h>

#define H   32
#define SEQ 2048
#define DH  128
#define NOUT 16
#define QMAXF 7.0f

// ---------------------------------------------------------------------------
// Scratch globals (K^T hi/lo in [h][d][s]; V hi/lo in [h][s][d])
// ---------------------------------------------------------------------------
__device__ __align__(16) __nv_bfloat16 g_khiT[(size_t)H * DH * SEQ];
__device__ __align__(16) __nv_bfloat16 g_kloT[(size_t)H * DH * SEQ];
__device__ __align__(16) __nv_bfloat16 g_vhi[(size_t)H * SEQ * DH];
__device__ __align__(16) __nv_bfloat16 g_vlo[(size_t)H * SEQ * DH];

// packed bf16x2 = {lo=a, hi=b}, round-nearest-even (same as __float2bfloat16_rn)
__device__ __forceinline__ uint32_t cvtpack(float a, float b) {
    uint32_t r;
    asm("cvt.rn.bf16x2.f32 %0, %2, %1;" : "=r"(r) : "f"(a), "f"(b));
    return r;
}
__device__ __forceinline__ float2 unpack_bf(uint32_t u) {
    __nv_bfloat162 t;
    *reinterpret_cast<uint32_t*>(&t) = u;
    return __bfloat1622float2(t);
}
__device__ __forceinline__ uint32_t smem_u32(const void* p) {
    uint32_t a;
    asm("{ .reg .u64 t; cvta.to.shared.u64 t, %1; cvt.u32.u64 %0, t; }" : "=r"(a) : "l"(p));
    return a;
}
// transposed ldmatrix: B operand from [k][n]-major smem
__device__ __forceinline__ void ldmx4t(uint32_t& r0, uint32_t& r1, uint32_t& r2, uint32_t& r3,
                                       uint32_t addr) {
    asm volatile("ldmatrix.sync.aligned.m8n8.x4.trans.shared.b16 {%0,%1,%2,%3}, [%4];"
                 : "=r"(r0), "=r"(r1), "=r"(r2), "=r"(r3) : "r"(addr));
}
__device__ __forceinline__ void mma_bf16(float* c, const uint32_t* a, uint32_t b0, uint32_t b1) {
    asm volatile("mma.sync.aligned.m16n8k16.row.col.f32.bf16.bf16.f32 "
                 "{%0,%1,%2,%3}, {%4,%5,%6,%7}, {%8,%9}, {%0,%1,%2,%3};"
                 : "+f"(c[0]), "+f"(c[1]), "+f"(c[2]), "+f"(c[3])
                 : "r"(a[0]), "r"(a[1]), "r"(a[2]), "r"(a[3]), "r"(b0), "r"(b1));
}
#define CP_ASYNC16(dst, src) do { \
    size_t _g = __cvta_generic_to_global((const void*)(src)); \
    asm volatile("cp.async.cg.shared.global [%0], [%1], 16;" :: "r"(dst), "l"(_g) : "memory"); \
} while (0)
#define CP_COMMIT() asm volatile("cp.async.commit_group;" ::: "memory")
#define CP_WAIT0()  asm volatile("cp.async.wait_group 0;" ::: "memory")
#define CP_WAIT1()  asm volatile("cp.async.wait_group 1;" ::: "memory")
#define GBAR(id)    asm volatile("bar.sync %0, 64;" :: "r"(id) : "memory")

extern __shared__ char sm_dyn[];

// ---------------------------------------------------------------------------
// K quantization, coalesced 4-slice version. One 256-thread block handles
// slices (h, d0..d0+3) via float4 loads. Each 64-thread group owns one slice
// (named barriers). Dynamic smem: sval[4][2048] + sabs[4][2048] = 64 KB.
// Writes K^T hi/lo [h][d][s] (coalesced).
// ---------------------------------------------------------------------------
#define KQ_SMEM 65536

__global__ __launch_bounds__(256) void kquant_kernel(const float* __restrict__ kin) {
    float* sval = (float*)sm_dyn;             // [4][2048]
    float* sabs = sval + 4 * SEQ;             // [4][2048]; flagged -> -1
    __shared__ float swv[8];
    __shared__ int   swi[8];
    __shared__ int   sgi[4];
    __shared__ float sgv[4];

    const int b = blockIdx.x;
    const int h = b >> 5;
    const int d0 = (b & 31) * 4;
    const int tid = threadIdx.x;
    const int lane = tid & 31, wid = tid >> 5;
    const int g = tid >> 6;                   // slice group 0..3
    const int l = tid & 63;                   // lane within group

    // ---- coalesced load: each thread reads 8 float4 rows ----
    const float* base = kin + (size_t)h * SEQ * DH + d0;
#pragma unroll
    for (int j = 0; j < 8; ++j) {
        int r = tid + 256 * j;
        float4 v = *(const float4*)(base + (size_t)r * DH);
        sval[0 * SEQ + r] = v.x; sabs[0 * SEQ + r] = fabsf(v.x);
        sval[1 * SEQ + r] = v.y; sabs[1 * SEQ + r] = fabsf(v.y);
        sval[2 * SEQ + r] = v.z; sabs[2 * SEQ + r] = fabsf(v.z);
        sval[3 * SEQ + r] = v.w; sabs[3 * SEQ + r] = fabsf(v.w);
    }
    __syncthreads();

    // ---- local argmax over this thread's 32 elements of slice g ----
    const float* gabs = sabs + g * SEQ;
    float amax = -1.0f; int aidx = 0;
#pragma unroll
    for (int j = 0; j < 32; ++j) {
        int i = l + 64 * j;
        float a = gabs[i];
        if (a > amax) { amax = a; aidx = i; }
    }

    // ---- 16 outlier passes, group-local ----
    for (int it = 0; it < NOUT; ++it) {
        float bv = amax; int bi = aidx;
#pragma unroll
        for (int o = 16; o > 0; o >>= 1) {
            float ov = __shfl_xor_sync(0xffffffffu, bv, o);
            int   oi = __shfl_xor_sync(0xffffffffu, bi, o);
            if (ov > bv || (ov == bv && oi < bi)) { bv = ov; bi = oi; }
        }
        if (lane == 0) { swv[wid] = bv; swi[wid] = bi; }
        GBAR(g + 1);
        if (l == 0) {
            float v0 = swv[2 * g], v1 = swv[2 * g + 1];
            int   i0 = swi[2 * g], i1 = swi[2 * g + 1];
            sgi[g] = (v1 > v0 || (v1 == v0 && i1 < i0)) ? i1 : i0;
        }
        GBAR(g + 1);
        int gw = sgi[g];
        if ((gw & 63) == l) {
            sabs[g * SEQ + gw] = -1.0f;
            amax = -1.0f; aidx = 0;
#pragma unroll
            for (int j = 0; j < 32; ++j) {
                int i = l + 64 * j;
                float a = gabs[i];
                if (a > amax) { amax = a; aidx = i; }
            }
        }
        GBAR(g + 1);   // winner's sabs update + rescan visible before next pass
    }

    // ---- dense max over remaining ----
    {
        float bv = amax;
#pragma unroll
        for (int o = 16; o > 0; o >>= 1) bv = fmaxf(bv, __shfl_xor_sync(0xffffffffu, bv, o));
        if (lane == 0) swv[wid] = bv;
        GBAR(g + 1);
        if (l == 0) sgv[g] = fmaxf(swv[2 * g], swv[2 * g + 1]);
        GBAR(g + 1);
    }
    const float scale = fmaxf(sgv[g], 1e-6f) / QMAXF;

    // ---- quantize + split + coalesced store ----
    __nv_bfloat16* khT = g_khiT + ((size_t)h * DH + d0 + g) * SEQ;
    __nv_bfloat16* klT = g_kloT + ((size_t)h * DH + d0 + g) * SEQ;
    const float* gval = sval + g * SEQ;
#pragma unroll
    for (int j = 0; j < 32; ++j) {
        int i = l + 64 * j;
        float v = gval[i];
        float o;
        if (gabs[i] < 0.0f) o = v;                        // outlier, exact
        else {
            float qq = rintf(__fdiv_rn(v, scale));
            qq = fminf(fmaxf(qq, -QMAXF), QMAXF);
            o = qq * scale;
        }
        __nv_bfloat16 hi = __float2bfloat16_rn(o);
        __nv_bfloat16 lo = __float2bfloat16_rn(o - __bfloat162float(hi));
        khT[i] = hi;
        klT[i] = lo;
    }
}

// ---------------------------------------------------------------------------
// V quantization + bf16 split, fused. One 128-thread block per (h, s) row.
// Writes V hi/lo [h][s][d] (coalesced).
// ---------------------------------------------------------------------------
__global__ __launch_bounds__(128) void vquant_kernel(const float* __restrict__ vin) {
    const int row = blockIdx.x;
    const int tid = threadIdx.x;

    float v = vin[(size_t)row * DH + tid];
    float a = fabsf(v);

    __shared__ float sab[DH];
    sab[tid] = a;
    __syncthreads();

    int rank = 0;
#pragma unroll 8
    for (int j = 0; j < DH; ++j) {
        float b = sab[j];
        rank += (b > a) || (b == a && j < tid);
    }
    const bool outl = (rank < NOUT);

    float da = outl ? 0.0f : a;
#pragma unroll
    for (int o = 16; o > 0; o >>= 1) da = fmaxf(da, __shfl_xor_sync(0xffffffffu, da, o));
    __shared__ float wmax[4];
    if ((tid & 31) == 0) wmax[tid >> 5] = da;
    __syncthreads();
    float mx = fmaxf(fmaxf(wmax[0], wmax[1]), fmaxf(wmax[2], wmax[3]));
    float scale = fmaxf(mx, 1e-6f) / QMAXF;

    float o;
    if (outl) o = v;
    else {
        float qq = rintf(__fdiv_rn(v, scale));
        qq = fminf(fmaxf(qq, -QMAXF), QMAXF);
        o = qq * scale;
    }
    __nv_bfloat16 hi = __float2bfloat16_rn(o);
    __nv_bfloat16 lo = __float2bfloat16_rn(o - __bfloat162float(hi));
    g_vhi[(size_t)row * DH + tid] = hi;
    g_vlo[(size_t)row * DH + tid] = lo;
}

// ---------------------------------------------------------------------------
// FA2 split-bf16 mma.sync flash attention; B operands via ldmatrix.x4.trans.
// Block = 128 threads (4 warps), BM = 64, BN = 64, D = 128, 71680 B smem,
// 2 blocks/SM. In-place cp.async phase pipeline (K under PV, V under QK).
// smem: sKT hi/lo [128 d][144B] @0/@18432;  sV hi/lo [64 s][272B] @36864/@54272
// ---------------------------------------------------------------------------
#define SKT_HI 0
#define SKT_LO 18432
#define SV_HI  36864
#define SV_LO  54272
#define ATTN_SMEM 71680
#define KTSTR 144
#define VSTR  272

__global__ __launch_bounds__(128, 2)
void attn_mma_kernel(const float* __restrict__ qin, float* __restrict__ out) {
    const uint32_t sb = smem_u32(sm_dyn);
    const int tid  = threadIdx.x;
    const int w    = tid >> 5;
    const int lane = tid & 31;
    const int bx = blockIdx.x;
    const int h  = bx & 31;
    const int qt = 31 - (bx >> 5);          // heavy tiles first
    const int qglob = qt * 64;

    const int quad = lane >> 2;
    const int qtr  = lane & 3;
    const int r0 = w * 16 + quad;
    const int rowg0 = qglob + r0;
    const int rowg1 = rowg0 + 8;

    const __nv_bfloat16* khi_h = g_khiT + (size_t)h * DH * SEQ;  // [d][s]
    const __nv_bfloat16* klo_h = g_kloT + (size_t)h * DH * SEQ;
    const __nv_bfloat16* vhi_h = g_vhi + (size_t)h * SEQ * DH;   // [s][d]
    const __nv_bfloat16* vlo_h = g_vlo + (size_t)h * SEQ * DH;

    // --- async tile loaders (16 cp.async per thread each) ---
    auto issue_k = [&](int kt) {   // K^T tile: 128 d-rows x 64 s (128B data/row)
        const __nv_bfloat16* kb0 = khi_h + (size_t)kt * 64;
        const __nv_bfloat16* kb1 = klo_h + (size_t)kt * 64;
#pragma unroll
        for (int i = tid; i < 1024; i += 128) {
            int r = i >> 3, c = i & 7;
            uint32_t sa = r * KTSTR + c * 16;
            CP_ASYNC16(sb + SKT_HI + sa, (const uint4*)(kb0 + (size_t)r * SEQ) + c);
            CP_ASYNC16(sb + SKT_LO + sa, (const uint4*)(kb1 + (size_t)r * SEQ) + c);
        }
    };
    auto issue_v = [&](int kt) {   // V tile: 64 s-rows x 128 d (256B data/row)
        const uint4* vb0 = (const uint4*)(vhi_h + (size_t)kt * 64 * DH);
        const uint4* vb1 = (const uint4*)(vlo_h + (size_t)kt * 64 * DH);
#pragma unroll
        for (int i = tid; i < 1024; i += 128) {
            int r = i >> 4, c = i & 15;
            uint32_t sa = r * VSTR + c * 16;
            CP_ASYNC16(sb + SV_HI + sa, vb0 + r * 16 + c);
            CP_ASYNC16(sb + SV_LO + sa, vb1 + r * 16 + c);
        }
    };

    // prologue: K(0) in flight while we stage Q
    issue_k(0);
    CP_COMMIT();

    // ---- stage Q (scaled) fp32 into the V region, build A-fragments ----
    float* sQf = (float*)(sm_dyn + SV_HI);  // [64][132], 33792 B <= 34816
    {
        const float sms = 0.08838834764831845f;
        const float4* qbase = (const float4*)(qin + ((size_t)h * SEQ + qglob) * DH);
        for (int i = tid; i < 64 * 32; i += 128) {
            int r = i >> 5, c = i & 31;
            float4 v = qbase[r * 32 + c];
            v.x *= sms; v.y *= sms; v.z *= sms; v.w *= sms;
            *(float4*)&sQf[r * 132 + c * 4] = v;
        }
    }
    __syncthreads();

    uint32_t qhi[8][4], qlo[8][4];
    {
        const float* s0 = &sQf[r0 * 132];
        const float* s1 = &sQf[(r0 + 8) * 132];
#pragma unroll
        for (int kf = 0; kf < 8; ++kf) {
            int k0 = kf * 16 + 2 * qtr;
            float e[4][2] = {{s0[k0], s0[k0 + 1]}, {s1[k0], s1[k0 + 1]},
                             {s0[k0 + 8], s0[k0 + 9]}, {s1[k0 + 8], s1[k0 + 9]}};
#pragma unroll
            for (int j = 0; j < 4; ++j) {
                uint32_t hp = cvtpack(e[j][0], e[j][1]);
                float2 hf = unpack_bf(hp);
                qhi[kf][j] = hp;
                qlo[kf][j] = cvtpack(e[j][0] - hf.x, e[j][1] - hf.y);
            }
        }
    }
    __syncthreads();   // Q staging done; V region may now be overwritten

    // trans-ldmatrix bases: lane l reads row (k-window + l) of the [k][n] tile
    const uint32_t kmt_h = sb + SKT_HI + lane * KTSTR;
    const uint32_t kmt_l = sb + SKT_LO + lane * KTSTR;
    const uint32_t vmt_h = sb + SV_HI + lane * VSTR;
    const uint32_t vmt_l = sb + SV_LO + lane * VSTR;

    float O[16][4];
#pragma unroll
    for (int i = 0; i < 16; ++i)
#pragma unroll
        for (int j = 0; j < 4; ++j) O[i][j] = 0.0f;
    float m0 = -INFINITY, m1 = -INFINITY, l0 = 0.0f, l1 = 0.0f;

    for (int kt = 0; kt <= qt; ++kt) {
        // V(kt) underway while we run QK on K(kt)
        issue_v(kt);
        CP_COMMIT();
        CP_WAIT1();            // K(kt) complete; V(kt) still in flight
        __syncthreads();

        // ---- S = Q K^T : 8 n-frags, 4 k-windows of 32, 3-term split ----
        float Sc[8][4];
#pragma unroll
        for (int nf = 0; nf < 8; ++nf) {
            Sc[nf][0] = Sc[nf][1] = Sc[nf][2] = Sc[nf][3] = 0.0f;
            uint32_t nof = nf * 16;                       // n-block byte offset
#pragma unroll
            for (int kf2 = 0; kf2 < 4; ++kf2) {
                uint32_t koff = kf2 * 32 * KTSTR;
                uint32_t h0, h1, h2, h3, lo0, lo1, lo2, lo3;
                ldmx4t(h0, h1, h2, h3, kmt_h + koff + nof);
                ldmx4t(lo0, lo1, lo2, lo3, kmt_l + koff + nof);
                mma_bf16(Sc[nf], qhi[2 * kf2], h0, h1);
                mma_bf16(Sc[nf], qhi[2 * kf2], lo0, lo1);
                mma_bf16(Sc[nf], qlo[2 * kf2], h0, h1);
                mma_bf16(Sc[nf], qhi[2 * kf2 + 1], h2, h3);
                mma_bf16(Sc[nf], qhi[2 * kf2 + 1], lo2, lo3);
                mma_bf16(Sc[nf], qlo[2 * kf2 + 1], h2, h3);
            }
        }

        CP_WAIT0();            // V(kt) complete
        __syncthreads();       // all warps done reading K(kt) -> K region free

        // K(kt+1) underway while we run softmax + PV on V(kt)
        if (kt < qt) {
            issue_k(kt + 1);
            CP_COMMIT();
        }

        // ---- causal mask (diagonal tile only) ----
        if (kt == qt) {
            int cb = kt * 64 + 2 * qtr;
#pragma unroll
            for (int nf = 0; nf < 8; ++nf) {
                int c0 = cb + nf * 8, c1 = c0 + 1;
                if (c0 > rowg0) Sc[nf][0] = -1e30f;
                if (c1 > rowg0) Sc[nf][1] = -1e30f;
                if (c0 > rowg1) Sc[nf][2] = -1e30f;
                if (c1 > rowg1) Sc[nf][3] = -1e30f;
            }
        }

        // ---- online softmax ----
        float t0 = -INFINITY, t1 = -INFINITY;
#pragma unroll
        for (int nf = 0; nf < 8; ++nf) {
            t0 = fmaxf(t0, fmaxf(Sc[nf][0], Sc[nf][1]));
            t1 = fmaxf(t1, fmaxf(Sc[nf][2], Sc[nf][3]));
        }
        t0 = fmaxf(t0, __shfl_xor_sync(0xffffffffu, t0, 1));
        t0 = fmaxf(t0, __shfl_xor_sync(0xffffffffu, t0, 2));
        t1 = fmaxf(t1, __shfl_xor_sync(0xffffffffu, t1, 1));
        t1 = fmaxf(t1, __shfl_xor_sync(0xffffffffu, t1, 2));
        float n0 = fmaxf(m0, t0), n1 = fmaxf(m1, t1);
        float c0 = __expf(m0 - n0), c1 = __expf(m1 - n1);
        m0 = n0; m1 = n1;

        float rs0 = 0.0f, rs1 = 0.0f;
#pragma unroll
        for (int nf = 0; nf < 8; ++nf) {
            Sc[nf][0] = __expf(Sc[nf][0] - n0);
            Sc[nf][1] = __expf(Sc[nf][1] - n0);
            Sc[nf][2] = __expf(Sc[nf][2] - n1);
            Sc[nf][3] = __expf(Sc[nf][3] - n1);
            rs0 += Sc[nf][0] + Sc[nf][1];
            rs1 += Sc[nf][2] + Sc[nf][3];
        }
        rs0 += __shfl_xor_sync(0xffffffffu, rs0, 1);
        rs0 += __shfl_xor_sync(0xffffffffu, rs0, 2);
        rs1 += __shfl_xor_sync(0xffffffffu, rs1, 1);
        rs1 += __shfl_xor_sync(0xffffffffu, rs1, 2);
        l0 = l0 * c0 + rs0;
        l1 = l1 * c1 + rs1;
#pragma unroll
        for (int i = 0; i < 16; ++i) {
            O[i][0] *= c0; O[i][1] *= c0;
            O[i][2] *= c1; O[i][3] *= c1;
        }

        // ---- P fragments (hi/lo split, packed cvt) ----
        uint32_t phi[4][4], plo[4][4];
#pragma unroll
        for (int kv = 0; kv < 4; ++kv) {
            const float* e0 = Sc[2 * kv];
            const float* e1 = Sc[2 * kv + 1];
            float src[4][2] = {{e0[0], e0[1]}, {e0[2], e0[3]}, {e1[0], e1[1]}, {e1[2], e1[3]}};
#pragma unroll
            for (int j = 0; j < 4; ++j) {
                uint32_t hp = cvtpack(src[j][0], src[j][1]);
                float2 hf = unpack_bf(hp);
                phi[kv][j] = hp;
                plo[kv][j] = cvtpack(src[j][0] - hf.x, src[j][1] - hf.y);
            }
        }

        // ---- O += P V : 16 n-frags over d, 2 k-windows of 32 over s ----
#pragma unroll
        for (int nf = 0; nf < 16; ++nf) {
            uint32_t nof = nf * 16;
#pragma unroll
            for (int kv2 = 0; kv2 < 2; ++kv2) {
                uint32_t koff = kv2 * 32 * VSTR;
                uint32_t h0, h1, h2, h3, lo0, lo1, lo2, lo3;
                ldmx4t(h0, h1, h2, h3, vmt_h + koff + nof);
                ldmx4t(lo0, lo1, lo2, lo3, vmt_l + koff + nof);
                mma_bf16(O[nf], phi[2 * kv2], h0, h1);
                mma_bf16(O[nf], phi[2 * kv2], lo0, lo1);
                mma_bf16(O[nf], plo[2 * kv2], h0, h1);
                mma_bf16(O[nf], phi[2 * kv2 + 1], h2, h3);
                mma_bf16(O[nf], phi[2 * kv2 + 1], lo2, lo3);
                mma_bf16(O[nf], plo[2 * kv2 + 1], h2, h3);
            }
        }
        __syncthreads();       // all warps done reading V(kt) before next issue_v
    }

    // ---- epilogue ----
    const float i0 = 1.0f / l0, i1 = 1.0f / l1;
    float* ob0 = out + ((size_t)h * SEQ + rowg0) * DH + 2 * qtr;
    float* ob1 = out + ((size_t)h * SEQ + rowg1) * DH + 2 * qtr;
#pragma unroll
    for (int nf = 0; nf < 16; ++nf) {
        float2 a; a.x = O[nf][0] * i0; a.y = O[nf][1] * i0;
        float2 b; b.x = O[nf][2] * i1; b.y = O[nf][3] * i1;
        *(float2*)(ob0 + nf * 8) = a;
        *(float2*)(ob1 + nf * 8) = b;
    }
}

// ---------------------------------------------------------------------------
extern "C" void kernel_launch(void* const* d_in, const int* in_sizes, int n_in,
                              void* d_out, int out_size) {
    const float* q = (const float*)d_in[0];
    const float* k = (const float*)d_in[1];
    const float* v = (const float*)d_in[2];
    float* out = (float*)d_out;

    cudaFuncSetAttribute(kquant_kernel, cudaFuncAttributeMaxDynamicSharedMemorySize, KQ_SMEM);
    kquant_kernel<<<H * 32, 256, KQ_SMEM>>>(k);
    vquant_kernel<<<H * SEQ, 128>>>(v);

    cudaFuncSetAttribute(attn_mma_kernel, cudaFuncAttributeMaxDynamicSharedMemorySize, ATTN_SMEM);
    attn_mma_kernel<<<H * 32, 128, ATTN_SMEM>>>(q, out);
}

// round 10
// speedup vs baseline: 1.8366x; 1.0673x over previous
#include <cuda_runtime.h>
#include <cuda_bf16.h>
#include <math.h>
#include <stdint.h>

#define H   32
#define SEQ 2048
#define DH  128
#define NOUT 16
#define QMAXF 7.0f

// ---------------------------------------------------------------------------
// Scratch globals (K^T hi/lo in [h][d][s]; V hi/lo in [h][s][d])
// ---------------------------------------------------------------------------
__device__ __align__(16) __nv_bfloat16 g_khiT[(size_t)H * DH * SEQ];
__device__ __align__(16) __nv_bfloat16 g_kloT[(size_t)H * DH * SEQ];
__device__ __align__(16) __nv_bfloat16 g_vhi[(size_t)H * SEQ * DH];
__device__ __align__(16) __nv_bfloat16 g_vlo[(size_t)H * SEQ * DH];

// packed bf16x2 = {lo=a, hi=b}, round-nearest-even
__device__ __forceinline__ uint32_t cvtpack(float a, float b) {
    uint32_t r;
    asm("cvt.rn.bf16x2.f32 %0, %2, %1;" : "=r"(r) : "f"(a), "f"(b));
    return r;
}
__device__ __forceinline__ float2 unpack_bf(uint32_t u) {
    __nv_bfloat162 t;
    *reinterpret_cast<uint32_t*>(&t) = u;
    return __bfloat1622float2(t);
}
__device__ __forceinline__ float ex2f(float x) {
    float r;
    asm("ex2.approx.f32 %0, %1;" : "=f"(r) : "f"(x));
    return r;
}
__device__ __forceinline__ uint32_t smem_u32(const void* p) {
    uint32_t a;
    asm("{ .reg .u64 t; cvta.to.shared.u64 t, %1; cvt.u32.u64 %0, t; }" : "=r"(a) : "l"(p));
    return a;
}
__device__ __forceinline__ void ldmx4t(uint32_t& r0, uint32_t& r1, uint32_t& r2, uint32_t& r3,
                                       uint32_t addr) {
    asm volatile("ldmatrix.sync.aligned.m8n8.x4.trans.shared.b16 {%0,%1,%2,%3}, [%4];"
                 : "=r"(r0), "=r"(r1), "=r"(r2), "=r"(r3) : "r"(addr));
}
__device__ __forceinline__ void mma_bf16(float* c, const uint32_t* a, uint32_t b0, uint32_t b1) {
    asm volatile("mma.sync.aligned.m16n8k16.row.col.f32.bf16.bf16.f32 "
                 "{%0,%1,%2,%3}, {%4,%5,%6,%7}, {%8,%9}, {%0,%1,%2,%3};"
                 : "+f"(c[0]), "+f"(c[1]), "+f"(c[2]), "+f"(c[3])
                 : "r"(a[0]), "r"(a[1]), "r"(a[2]), "r"(a[3]), "r"(b0), "r"(b1));
}
#define CP_ASYNC16(dst, src) do { \
    size_t _g = __cvta_generic_to_global((const void*)(src)); \
    asm volatile("cp.async.cg.shared.global [%0], [%1], 16;" :: "r"(dst), "l"(_g) : "memory"); \
} while (0)
#define CP_COMMIT() asm volatile("cp.async.commit_group;" ::: "memory")
#define CP_WAIT0()  asm volatile("cp.async.wait_group 0;" ::: "memory")
#define CP_WAIT1()  asm volatile("cp.async.wait_group 1;" ::: "memory")
#define GBAR(id)    asm volatile("bar.sync %0, 64;" :: "r"(id) : "memory")

extern __shared__ char sm_dyn[];

// ---------------------------------------------------------------------------
// K quantization, coalesced 4-slice version, values in registers.
// One 256-thread block handles slices (h, d0..d0+3) via float4 loads.
// Each 64-thread group owns one slice's argmax (named barriers).
// Dynamic smem: sabs[4][2048] = 32 KB only.
// ---------------------------------------------------------------------------
#define KQ_SMEM 32768

__global__ __launch_bounds__(256, 4) void kquant_kernel(const float* __restrict__ kin) {
    float* sabs = (float*)sm_dyn;             // [4][2048]; flagged -> -1
    __shared__ float swv[8];
    __shared__ int   swi[8];
    __shared__ int   sgi[4];
    __shared__ float sgv[4];

    const int b = blockIdx.x;
    const int h = b >> 5;
    const int d0 = (b & 31) * 4;
    const int tid = threadIdx.x;
    const int lane = tid & 31, wid = tid >> 5;
    const int g = tid >> 6;                   // slice group 0..3
    const int l = tid & 63;                   // lane within group

    // ---- coalesced load: values stay in registers; abs goes to smem ----
    const float* base = kin + (size_t)h * SEQ * DH + d0;
    float4 vals[8];
#pragma unroll
    for (int j = 0; j < 8; ++j) {
        int r = tid + 256 * j;
        float4 v = *(const float4*)(base + (size_t)r * DH);
        vals[j] = v;
        sabs[0 * SEQ + r] = fabsf(v.x);
        sabs[1 * SEQ + r] = fabsf(v.y);
        sabs[2 * SEQ + r] = fabsf(v.z);
        sabs[3 * SEQ + r] = fabsf(v.w);
    }
    __syncthreads();

    // ---- local argmax over this thread's 32 elements of slice g ----
    const float* gabs = sabs + g * SEQ;
    float amax = -1.0f; int aidx = 0;
#pragma unroll
    for (int j = 0; j < 32; ++j) {
        int i = l + 64 * j;
        float a = gabs[i];
        if (a > amax) { amax = a; aidx = i; }
    }

    // ---- 16 outlier passes, group-local ----
    for (int it = 0; it < NOUT; ++it) {
        float bv = amax; int bi = aidx;
#pragma unroll
        for (int o = 16; o > 0; o >>= 1) {
            float ov = __shfl_xor_sync(0xffffffffu, bv, o);
            int   oi = __shfl_xor_sync(0xffffffffu, bi, o);
            if (ov > bv || (ov == bv && oi < bi)) { bv = ov; bi = oi; }
        }
        if (lane == 0) { swv[wid] = bv; swi[wid] = bi; }
        GBAR(g + 1);
        if (l == 0) {
            float v0 = swv[2 * g], v1 = swv[2 * g + 1];
            int   i0 = swi[2 * g], i1 = swi[2 * g + 1];
            sgi[g] = (v1 > v0 || (v1 == v0 && i1 < i0)) ? i1 : i0;
        }
        GBAR(g + 1);
        int gw = sgi[g];
        if ((gw & 63) == l) {
            sabs[g * SEQ + gw] = -1.0f;
            amax = -1.0f; aidx = 0;
#pragma unroll
            for (int j = 0; j < 32; ++j) {
                int i = l + 64 * j;
                float a = gabs[i];
                if (a > amax) { amax = a; aidx = i; }
            }
        }
        GBAR(g + 1);
    }

    // ---- dense max over remaining, then block-wide scale publish ----
    {
        float bv = amax;
#pragma unroll
        for (int o = 16; o > 0; o >>= 1) bv = fmaxf(bv, __shfl_xor_sync(0xffffffffu, bv, o));
        if (lane == 0) swv[wid] = bv;
        GBAR(g + 1);
        if (l == 0) sgv[g] = fmaxf(swv[2 * g], swv[2 * g + 1]);
    }
    __syncthreads();   // all four sgv[] visible to every thread

    float sc[4];
#pragma unroll
    for (int c = 0; c < 4; ++c) sc[c] = fmaxf(sgv[c], 1e-6f) / QMAXF;

    // ---- quantize + split + coalesced store (4 slices per thread) ----
#pragma unroll
    for (int j = 0; j < 8; ++j) {
        int r = tid + 256 * j;
        float vv[4] = {vals[j].x, vals[j].y, vals[j].z, vals[j].w};
#pragma unroll
        for (int c = 0; c < 4; ++c) {
            float v = vv[c];
            float o;
            if (sabs[c * SEQ + r] < 0.0f) o = v;          // outlier, exact
            else {
                float qq = rintf(__fdiv_rn(v, sc[c]));
                qq = fminf(fmaxf(qq, -QMAXF), QMAXF);
                o = qq * sc[c];
            }
            __nv_bfloat16 hi = __float2bfloat16_rn(o);
            __nv_bfloat16 lo = __float2bfloat16_rn(o - __bfloat162float(hi));
            size_t oidx = ((size_t)h * DH + d0 + c) * SEQ + r;
            g_khiT[oidx] = hi;
            g_kloT[oidx] = lo;
        }
    }
}

// ---------------------------------------------------------------------------
// V quantization + bf16 split, fused. One 128-thread block per (h, s) row.
// ---------------------------------------------------------------------------
__global__ __launch_bounds__(128) void vquant_kernel(const float* __restrict__ vin) {
    const int row = blockIdx.x;
    const int tid = threadIdx.x;

    float v = vin[(size_t)row * DH + tid];
    float a = fabsf(v);

    __shared__ float sab[DH];
    sab[tid] = a;
    __syncthreads();

    int rank = 0;
#pragma unroll 8
    for (int j = 0; j < DH; ++j) {
        float b = sab[j];
        rank += (b > a) || (b == a && j < tid);
    }
    const bool outl = (rank < NOUT);

    float da = outl ? 0.0f : a;
#pragma unroll
    for (int o = 16; o > 0; o >>= 1) da = fmaxf(da, __shfl_xor_sync(0xffffffffu, da, o));
    __shared__ float wmax[4];
    if ((tid & 31) == 0) wmax[tid >> 5] = da;
    __syncthreads();
    float mx = fmaxf(fmaxf(wmax[0], wmax[1]), fmaxf(wmax[2], wmax[3]));
    float scale = fmaxf(mx, 1e-6f) / QMAXF;

    float o;
    if (outl) o = v;
    else {
        float qq = rintf(__fdiv_rn(v, scale));
        qq = fminf(fmaxf(qq, -QMAXF), QMAXF);
        o = qq * scale;
    }
    __nv_bfloat16 hi = __float2bfloat16_rn(o);
    __nv_bfloat16 lo = __float2bfloat16_rn(o - __bfloat162float(hi));
    g_vhi[(size_t)row * DH + tid] = hi;
    g_vlo[(size_t)row * DH + tid] = lo;
}

// ---------------------------------------------------------------------------
// FA2 split-bf16 mma.sync flash attention; B operands via ldmatrix.x4.trans.
// Softmax in exp2 domain (Q pre-scaled by 1/sqrt(d) * log2(e)).
// Block = 128 threads (4 warps), BM = 64, BN = 64, D = 128, 71680 B smem,
// 3 blocks/SM target. In-place cp.async phase pipeline.
// ---------------------------------------------------------------------------
#define SKT_HI 0
#define SKT_LO 18432
#define SV_HI  36864
#define SV_LO  54272
#define ATTN_SMEM 71680
#define KTSTR 144
#define VSTR  272

__global__ __launch_bounds__(128, 3)
void attn_mma_kernel(const float* __restrict__ qin, float* __restrict__ out) {
    const uint32_t sb = smem_u32(sm_dyn);
    const int tid  = threadIdx.x;
    const int w    = tid >> 5;
    const int lane = tid & 31;
    const int bx = blockIdx.x;
    const int h  = bx & 31;
    const int qt = 31 - (bx >> 5);          // heavy tiles first
    const int qglob = qt * 64;

    const int quad = lane >> 2;
    const int qtr  = lane & 3;
    const int r0 = w * 16 + quad;
    const int rowg0 = qglob + r0;
    const int rowg1 = rowg0 + 8;

    const __nv_bfloat16* khi_h = g_khiT + (size_t)h * DH * SEQ;  // [d][s]
    const __nv_bfloat16* klo_h = g_kloT + (size_t)h * DH * SEQ;
    const __nv_bfloat16* vhi_h = g_vhi + (size_t)h * SEQ * DH;   // [s][d]
    const __nv_bfloat16* vlo_h = g_vlo + (size_t)h * SEQ * DH;

    auto issue_k = [&](int kt) {   // K^T tile: 128 d-rows x 64 s
        const __nv_bfloat16* kb0 = khi_h + (size_t)kt * 64;
        const __nv_bfloat16* kb1 = klo_h + (size_t)kt * 64;
#pragma unroll
        for (int i = tid; i < 1024; i += 128) {
            int r = i >> 3, c = i & 7;
            uint32_t sa = r * KTSTR + c * 16;
            CP_ASYNC16(sb + SKT_HI + sa, (const uint4*)(kb0 + (size_t)r * SEQ) + c);
            CP_ASYNC16(sb + SKT_LO + sa, (const uint4*)(kb1 + (size_t)r * SEQ) + c);
        }
    };
    auto issue_v = [&](int kt) {   // V tile: 64 s-rows x 128 d
        const uint4* vb0 = (const uint4*)(vhi_h + (size_t)kt * 64 * DH);
        const uint4* vb1 = (const uint4*)(vlo_h + (size_t)kt * 64 * DH);
#pragma unroll
        for (int i = tid; i < 1024; i += 128) {
            int r = i >> 4, c = i & 15;
            uint32_t sa = r * VSTR + c * 16;
            CP_ASYNC16(sb + SV_HI + sa, vb0 + r * 16 + c);
            CP_ASYNC16(sb + SV_LO + sa, vb1 + r * 16 + c);
        }
    };

    // prologue: K(0) in flight while we stage Q
    issue_k(0);
    CP_COMMIT();

    // ---- stage Q (scaled by 1/sqrt(d)*log2e) fp32, build A-fragments ----
    float* sQf = (float*)(sm_dyn + SV_HI);  // [64][132]
    {
        const float sms = 0.12751791677269355f;   // 0.088388348 * 1.4426950409
        const float4* qbase = (const float4*)(qin + ((size_t)h * SEQ + qglob) * DH);
        for (int i = tid; i < 64 * 32; i += 128) {
            int r = i >> 5, c = i & 31;
            float4 v = qbase[r * 32 + c];
            v.x *= sms; v.y *= sms; v.z *= sms; v.w *= sms;
            *(float4*)&sQf[r * 132 + c * 4] = v;
        }
    }
    __syncthreads();

    uint32_t qhi[8][4], qlo[8][4];
    {
        const float* s0 = &sQf[r0 * 132];
        const float* s1 = &sQf[(r0 + 8) * 132];
#pragma unroll
        for (int kf = 0; kf < 8; ++kf) {
            int k0 = kf * 16 + 2 * qtr;
            float e[4][2] = {{s0[k0], s0[k0 + 1]}, {s1[k0], s1[k0 + 1]},
                             {s0[k0 + 8], s0[k0 + 9]}, {s1[k0 + 8], s1[k0 + 9]}};
#pragma unroll
            for (int j = 0; j < 4; ++j) {
                uint32_t hp = cvtpack(e[j][0], e[j][1]);
                float2 hf = unpack_bf(hp);
                qhi[kf][j] = hp;
                qlo[kf][j] = cvtpack(e[j][0] - hf.x, e[j][1] - hf.y);
            }
        }
    }
    __syncthreads();   // Q staging done; V region may now be overwritten

    const uint32_t kmt_h = sb + SKT_HI + lane * KTSTR;
    const uint32_t kmt_l = sb + SKT_LO + lane * KTSTR;
    const uint32_t vmt_h = sb + SV_HI + lane * VSTR;
    const uint32_t vmt_l = sb + SV_LO + lane * VSTR;

    float O[16][4];
#pragma unroll
    for (int i = 0; i < 16; ++i)
#pragma unroll
        for (int j = 0; j < 4; ++j) O[i][j] = 0.0f;
    float m0 = -INFINITY, m1 = -INFINITY, l0 = 0.0f, l1 = 0.0f;

    for (int kt = 0; kt <= qt; ++kt) {
        issue_v(kt);
        CP_COMMIT();
        CP_WAIT1();            // K(kt) complete; V(kt) still in flight
        __syncthreads();

        // ---- S = Q K^T (log2e domain) ----
        float Sc[8][4];
#pragma unroll
        for (int nf = 0; nf < 8; ++nf) {
            Sc[nf][0] = Sc[nf][1] = Sc[nf][2] = Sc[nf][3] = 0.0f;
            uint32_t nof = nf * 16;
#pragma unroll
            for (int kf2 = 0; kf2 < 4; ++kf2) {
                uint32_t koff = kf2 * 32 * KTSTR;
                uint32_t h0, h1, h2, h3, lo0, lo1, lo2, lo3;
                ldmx4t(h0, h1, h2, h3, kmt_h + koff + nof);
                ldmx4t(lo0, lo1, lo2, lo3, kmt_l + koff + nof);
                mma_bf16(Sc[nf], qhi[2 * kf2], h0, h1);
                mma_bf16(Sc[nf], qhi[2 * kf2], lo0, lo1);
                mma_bf16(Sc[nf], qlo[2 * kf2], h0, h1);
                mma_bf16(Sc[nf], qhi[2 * kf2 + 1], h2, h3);
                mma_bf16(Sc[nf], qhi[2 * kf2 + 1], lo2, lo3);
                mma_bf16(Sc[nf], qlo[2 * kf2 + 1], h2, h3);
            }
        }

        CP_WAIT0();            // V(kt) complete
        __syncthreads();       // all warps done reading K(kt)

        if (kt < qt) {
            issue_k(kt + 1);
            CP_COMMIT();
        }

        // ---- causal mask (diagonal tile only) ----
        if (kt == qt) {
            int cb = kt * 64 + 2 * qtr;
#pragma unroll
            for (int nf = 0; nf < 8; ++nf) {
                int c0 = cb + nf * 8, c1 = c0 + 1;
                if (c0 > rowg0) Sc[nf][0] = -1e30f;
                if (c1 > rowg0) Sc[nf][1] = -1e30f;
                if (c0 > rowg1) Sc[nf][2] = -1e30f;
                if (c1 > rowg1) Sc[nf][3] = -1e30f;
            }
        }

        // ---- online softmax (exp2 domain) ----
        float t0 = -INFINITY, t1 = -INFINITY;
#pragma unroll
        for (int nf = 0; nf < 8; ++nf) {
            t0 = fmaxf(t0, fmaxf(Sc[nf][0], Sc[nf][1]));
            t1 = fmaxf(t1, fmaxf(Sc[nf][2], Sc[nf][3]));
        }
        t0 = fmaxf(t0, __shfl_xor_sync(0xffffffffu, t0, 1));
        t0 = fmaxf(t0, __shfl_xor_sync(0xffffffffu, t0, 2));
        t1 = fmaxf(t1, __shfl_xor_sync(0xffffffffu, t1, 1));
        t1 = fmaxf(t1, __shfl_xor_sync(0xffffffffu, t1, 2));
        float n0 = fmaxf(m0, t0), n1 = fmaxf(m1, t1);
        float c0 = ex2f(m0 - n0), c1 = ex2f(m1 - n1);
        m0 = n0; m1 = n1;

        float rs0 = 0.0f, rs1 = 0.0f;
#pragma unroll
        for (int nf = 0; nf < 8; ++nf) {
            Sc[nf][0] = ex2f(Sc[nf][0] - n0);
            Sc[nf][1] = ex2f(Sc[nf][1] - n0);
            Sc[nf][2] = ex2f(Sc[nf][2] - n1);
            Sc[nf][3] = ex2f(Sc[nf][3] - n1);
            rs0 += Sc[nf][0] + Sc[nf][1];
            rs1 += Sc[nf][2] + Sc[nf][3];
        }
        rs0 += __shfl_xor_sync(0xffffffffu, rs0, 1);
        rs0 += __shfl_xor_sync(0xffffffffu, rs0, 2);
        rs1 += __shfl_xor_sync(0xffffffffu, rs1, 1);
        rs1 += __shfl_xor_sync(0xffffffffu, rs1, 2);
        l0 = l0 * c0 + rs0;
        l1 = l1 * c1 + rs1;
#pragma unroll
        for (int i = 0; i < 16; ++i) {
            O[i][0] *= c0; O[i][1] *= c0;
            O[i][2] *= c1; O[i][3] *= c1;
        }

        // ---- P fragments (hi/lo split, packed cvt) ----
        uint32_t phi[4][4], plo[4][4];
#pragma unroll
        for (int kv = 0; kv < 4; ++kv) {
            const float* e0 = Sc[2 * kv];
            const float* e1 = Sc[2 * kv + 1];
            float src[4][2] = {{e0[0], e0[1]}, {e0[2], e0[3]}, {e1[0], e1[1]}, {e1[2], e1[3]}};
#pragma unroll
            for (int j = 0; j < 4; ++j) {
                uint32_t hp = cvtpack(src[j][0], src[j][1]);
                float2 hf = unpack_bf(hp);
                phi[kv][j] = hp;
                plo[kv][j] = cvtpack(src[j][0] - hf.x, src[j][1] - hf.y);
            }
        }

        // ---- O += P V ----
#pragma unroll
        for (int nf = 0; nf < 16; ++nf) {
            uint32_t nof = nf * 16;
#pragma unroll
            for (int kv2 = 0; kv2 < 2; ++kv2) {
                uint32_t koff = kv2 * 32 * VSTR;
                uint32_t h0, h1, h2, h3, lo0, lo1, lo2, lo3;
                ldmx4t(h0, h1, h2, h3, vmt_h + koff + nof);
                ldmx4t(lo0, lo1, lo2, lo3, vmt_l + koff + nof);
                mma_bf16(O[nf], phi[2 * kv2], h0, h1);
                mma_bf16(O[nf], phi[2 * kv2], lo0, lo1);
                mma_bf16(O[nf], plo[2 * kv2], h0, h1);
                mma_bf16(O[nf], phi[2 * kv2 + 1], h2, h3);
                mma_bf16(O[nf], phi[2 * kv2 + 1], lo2, lo3);
                mma_bf16(O[nf], plo[2 * kv2 + 1], h2, h3);
            }
        }
        __syncthreads();       // all warps done reading V(kt)
    }

    // ---- epilogue ----
    const float i0 = 1.0f / l0, i1 = 1.0f / l1;
    float* ob0 = out + ((size_t)h * SEQ + rowg0) * DH + 2 * qtr;
    float* ob1 = out + ((size_t)h * SEQ + rowg1) * DH + 2 * qtr;
#pragma unroll
    for (int nf = 0; nf < 16; ++nf) {
        float2 a; a.x = O[nf][0] * i0; a.y = O[nf][1] * i0;
        float2 b; b.x = O[nf][2] * i1; b.y = O[nf][3] * i1;
        *(float2*)(ob0 + nf * 8) = a;
        *(float2*)(ob1 + nf * 8) = b;
    }
}

// ---------------------------------------------------------------------------
extern "C" void kernel_launch(void* const* d_in, const int* in_sizes, int n_in,
                              void* d_out, int out_size) {
    const float* q = (const float*)d_in[0];
    const float* k = (const float*)d_in[1];
    const float* v = (const float*)d_in[2];
    float* out = (float*)d_out;

    cudaFuncSetAttribute(kquant_kernel, cudaFuncAttributeMaxDynamicSharedMemorySize, KQ_SMEM);
    kquant_kernel<<<H * 32, 256, KQ_SMEM>>>(k);
    vquant_kernel<<<H * SEQ, 128>>>(v);

    cudaFuncSetAttribute(attn_mma_kernel, cudaFuncAttributeMaxDynamicSharedMemorySize, ATTN_SMEM);
    attn_mma_kernel<<<H * 32, 128, ATTN_SMEM>>>(q, out);
}